// round 3
// baseline (speedup 1.0000x reference)
#include <cuda_runtime.h>
#include <math.h>

// ---------------------------------------------------------------------------
// Scratch (no allocation allowed -> __device__ globals)
// Max live tensor: layer0 out 8*256*62401 = 127,797,248 floats (~511 MB)
//                  layer1 out 8*512*31201 = 127,799,296 floats (~511 MB)
// ---------------------------------------------------------------------------
__device__ float g_bufA[128000000];   // 512 MB ping
__device__ float g_bufB[128000000];   // 512 MB pong
__device__ float g_mean[512];
__device__ float g_istd[512];
__device__ float g_cnorm[1024];
__device__ int   g_idx[8192];

// ---------------------------------------------------------------------------
// Helpers
// ---------------------------------------------------------------------------
__device__ __forceinline__ float gelu_f(float x) {
    return 0.5f * x * (1.0f + erff(x * 0.7071067811865476f));
}

struct f32x2 { unsigned long long u; };

__device__ __forceinline__ f32x2 pack2(float lo, float hi) {
    f32x2 r; asm("mov.b64 %0, {%1, %2};" : "=l"(r.u) : "f"(lo), "f"(hi)); return r;
}
__device__ __forceinline__ void fma2(f32x2 &d, f32x2 a, f32x2 b) {
    asm("fma.rn.f32x2 %0, %1, %2, %0;" : "+l"(d.u) : "l"(a.u), "l"(b.u));
}
__device__ __forceinline__ void unpack2(f32x2 v, float &lo, float &hi) {
    asm("mov.b64 {%0, %1}, %2;" : "=f"(lo), "=f"(hi) : "l"(v.u));
}

// ---------------------------------------------------------------------------
// conv0: Cin=1, Cout=256, K=10, stride=5, pad=5  (cheap: 1.3e9 MAC)
// ---------------------------------------------------------------------------
__global__ __launch_bounds__(128)
void conv0_kernel(const float* __restrict__ x, const float* __restrict__ w,
                  const float* __restrict__ bias, float* __restrict__ y,
                  int Lin, int Lout)
{
    __shared__ float Wsh[2560];
    __shared__ float Bsh[256];
    __shared__ float Xsh[5 * 127 + 10];   // 645
    int b   = blockIdx.y;
    int l0  = blockIdx.x * 128;
    int tid = threadIdx.x;
    for (int i = tid; i < 2560; i += 128) Wsh[i] = w[i];
    for (int i = tid; i < 256;  i += 128) Bsh[i] = bias[i];
    int x0 = 5 * l0 - 5;
    for (int i = tid; i < 645; i += 128) {
        int gl = x0 + i;
        Xsh[i] = (gl >= 0 && gl < Lin) ? x[(size_t)b * Lin + gl] : 0.0f;
    }
    __syncthreads();
    int l = l0 + tid;
    if (l >= Lout) return;
    float xr[10];
    #pragma unroll
    for (int t = 0; t < 10; t++) xr[t] = Xsh[5 * tid + t];
    float* yb = y + (size_t)b * 256 * Lout + l;
    for (int co = 0; co < 256; co++) {
        float a = Bsh[co];
        #pragma unroll
        for (int t = 0; t < 10; t++) a = fmaf(Wsh[co * 10 + t], xr[t], a);
        yb[(size_t)co * Lout] = a;
    }
}

// ---------------------------------------------------------------------------
// Generic implicit-GEMM conv1d (also used for projection & VQ scores with KW=1)
// out[b][co][l] = bias[co] + sum_{ci,t} w[co][ci][t] * x[b][ci][STRIDE*l - PAD + t]
// CO_TILE=64, L_TILE=128, CI_T=8; 128 threads; thread tile 8co x 8l; f32x2 FMA.
// ---------------------------------------------------------------------------
#define CO_TILE 64
#define L_TILE  128
#define CI_T    8

template<int KW, int STRIDE, int PAD, bool TRANS_OUT>
__global__ __launch_bounds__(128)
void conv_gemm(const float* __restrict__ x, const float* __restrict__ w,
               const float* __restrict__ bias, float* __restrict__ y,
               int Cin, int Cout, int Lin, int Lout)
{
    constexpr int SPAN = STRIDE * (L_TILE - 1) + KW;
    __shared__ float Ws[CO_TILE][CI_T * KW + 1];  // +1 pad: kill bank conflicts
    __shared__ float Xs[CI_T][SPAN];

    int b      = blockIdx.z;
    int co0    = blockIdx.y * CO_TILE;
    int l0     = blockIdx.x * L_TILE;
    int tid    = threadIdx.x;
    int co_sub = tid >> 4;   // 0..7
    int l_sub  = tid & 15;   // 0..15
    int x_start = STRIDE * l0 - PAD;
    const float* xb = x + (size_t)b * Cin * Lin;

    f32x2 acc[8][4];
    #pragma unroll
    for (int i = 0; i < 8; i++)
        #pragma unroll
        for (int m = 0; m < 4; m++) acc[i][m].u = 0ull;

    for (int ci0 = 0; ci0 < Cin; ci0 += CI_T) {
        __syncthreads();
        for (int idx = tid; idx < CO_TILE * CI_T * KW; idx += 128) {
            int row = idx / (CI_T * KW);
            int k   = idx - row * (CI_T * KW);
            Ws[row][k] = w[(size_t)(co0 + row) * Cin * KW + (size_t)ci0 * KW + k];
        }
        for (int idx = tid; idx < CI_T * SPAN; idx += 128) {
            int row = idx / SPAN;
            int col = idx - row * SPAN;
            int gl  = x_start + col;
            float v = 0.0f;
            if (gl >= 0 && gl < Lin) v = xb[(size_t)(ci0 + row) * Lin + gl];
            Xs[row][col] = v;
        }
        __syncthreads();

        #pragma unroll 2
        for (int ci = 0; ci < CI_T; ci++) {
            #pragma unroll
            for (int t = 0; t < KW; t++) {
                f32x2 w2[8];
                #pragma unroll
                for (int i = 0; i < 8; i++) {
                    float wv = Ws[co_sub * 8 + i][ci * KW + t];
                    w2[i] = pack2(wv, wv);
                }
                f32x2 x2[4];
                #pragma unroll
                for (int m = 0; m < 4; m++) {
                    float a = Xs[ci][STRIDE * (l_sub + 32 * m) + t];
                    float c = Xs[ci][STRIDE * (l_sub + 32 * m + 16) + t];
                    x2[m] = pack2(a, c);
                }
                #pragma unroll
                for (int i = 0; i < 8; i++)
                    #pragma unroll
                    for (int m = 0; m < 4; m++) fma2(acc[i][m], w2[i], x2[m]);
            }
        }
    }

    #pragma unroll
    for (int i = 0; i < 8; i++) {
        int co = co0 + co_sub * 8 + i;
        float bv = bias ? bias[co] : 0.0f;
        #pragma unroll
        for (int m = 0; m < 4; m++) {
            float v0, v1;
            unpack2(acc[i][m], v0, v1);
            int la = l0 + l_sub + 32 * m;
            int lb = la + 16;
            if (TRANS_OUT) {
                if (la < Lout) y[((size_t)b * Lout + la) * Cout + co] = v0 + bv;
                if (lb < Lout) y[((size_t)b * Lout + lb) * Cout + co] = v1 + bv;
            } else {
                float* yr = y + ((size_t)b * Cout + co) * Lout;
                if (la < Lout) yr[la] = v0 + bv;
                if (lb < Lout) yr[lb] = v1 + bv;
            }
        }
    }
}

// ---------------------------------------------------------------------------
// GroupNorm stats: one block per (b, group); group data is contiguous.
// ---------------------------------------------------------------------------
__global__ __launch_bounds__(256)
void gn_stats(const float* __restrict__ y, float* __restrict__ mean,
              float* __restrict__ istd, long long nPer)
{
    long long base = (long long)blockIdx.x * nPer;   // multiple of 16 floats
    const float4* y4 = (const float4*)(y + base);
    long long n4 = nPer >> 2;
    float s = 0.0f, s2 = 0.0f;
    for (long long i = threadIdx.x; i < n4; i += 256) {
        float4 v = y4[i];
        s  += v.x + v.y + v.z + v.w;
        s2 = fmaf(v.x, v.x, s2); s2 = fmaf(v.y, v.y, s2);
        s2 = fmaf(v.z, v.z, s2); s2 = fmaf(v.w, v.w, s2);
    }
    __shared__ float sa[256], sb[256];
    int tid = threadIdx.x;
    sa[tid] = s; sb[tid] = s2;
    __syncthreads();
    for (int o = 128; o > 0; o >>= 1) {
        if (tid < o) { sa[tid] += sa[tid + o]; sb[tid] += sb[tid + o]; }
        __syncthreads();
    }
    if (tid == 0) {
        float m   = sa[0] / (float)nPer;
        float var = sb[0] / (float)nPer - m * m;
        mean[blockIdx.x] = m;
        istd[blockIdx.x] = rsqrtf(var + 1e-5f);
    }
}

// ---------------------------------------------------------------------------
// Apply GN affine + exact GELU. grid = (ceil(L/256), C, B) -> no divides.
// ---------------------------------------------------------------------------
__global__ __launch_bounds__(256)
void norm_gelu(float* __restrict__ y, const float* __restrict__ mean,
               const float* __restrict__ istd, const float* __restrict__ gma,
               const float* __restrict__ bta, int L, int G, int chPerG)
{
    int c = blockIdx.y, b = blockIdx.z;
    int l = blockIdx.x * 256 + threadIdx.x;
    if (l >= L) return;
    int bg = b * G + c / chPerG;
    size_t i = ((size_t)b * gridDim.y + c) * L + l;
    float v = y[i];
    v = (v - mean[bg]) * istd[bg] * gma[c] + bta[c];
    y[i] = gelu_f(v);
}

// ---------------------------------------------------------------------------
// Codebook row squared norms
// ---------------------------------------------------------------------------
__global__ __launch_bounds__(256)
void cb_norms(const float* __restrict__ cb, float* __restrict__ cn)
{
    const float4* row = (const float4*)(cb + (size_t)blockIdx.x * 1536);
    float s = 0.0f;
    for (int i = threadIdx.x; i < 384; i += 256) {
        float4 v = row[i];
        s += v.x * v.x + v.y * v.y + v.z * v.z + v.w * v.w;
    }
    __shared__ float sa[256];
    int tid = threadIdx.x;
    sa[tid] = s;
    __syncthreads();
    for (int o = 128; o > 0; o >>= 1) {
        if (tid < o) sa[tid] += sa[tid + o];
        __syncthreads();
    }
    if (tid == 0) cn[blockIdx.x] = sa[0];
}

// ---------------------------------------------------------------------------
// Argmin over 1024 codes per position; first-index tie break (matches jnp.argmin)
// scores layout: [n][1024]
// ---------------------------------------------------------------------------
__global__ __launch_bounds__(256)
void vq_argmin(const float* __restrict__ sc, const float* __restrict__ cn,
               int* __restrict__ idx, int NS)
{
    int g = blockIdx.x * 8 + (threadIdx.x >> 5);
    int lane = threadIdx.x & 31;
    if (g >= NS) return;
    const float* s = sc + (size_t)g * 1024;
    float best = 3.4e38f; int bi = 1 << 30;
    for (int j = lane; j < 1024; j += 32) {
        float d = fmaf(-2.0f, s[j], cn[j]);
        if (d < best) { best = d; bi = j; }   // j increasing -> keeps first on ties
    }
    #pragma unroll
    for (int o = 16; o > 0; o >>= 1) {
        float ov = __shfl_xor_sync(0xffffffffu, best, o);
        int   oi = __shfl_xor_sync(0xffffffffu, bi,   o);
        if (ov < best || (ov == best && oi < bi)) { best = ov; bi = oi; }
    }
    if (lane == 0) idx[g] = bi;
}

// ---------------------------------------------------------------------------
// Final: q = codebook[idx] + pos + modality ; LayerNorm ; write emb, mask, idx
// ---------------------------------------------------------------------------
__global__ __launch_bounds__(256)
void final_ln(const float* __restrict__ cb, const int* __restrict__ idx,
              const float* __restrict__ pos, const float* __restrict__ mod,
              const float* __restrict__ lng, const float* __restrict__ lnb,
              float* __restrict__ out, int S, int NS)
{
    int n = blockIdx.x;
    int s = n % S;
    int tid = threadIdx.x;
    __shared__ float row[1536];
    __shared__ float sa[256], sb[256];
    const float* c = cb  + (size_t)idx[n] * 1536;
    const float* p = pos + (size_t)s      * 1536;
    float ls = 0.0f, ls2 = 0.0f;
    for (int e = tid; e < 1536; e += 256) {
        float v = c[e] + p[e] + mod[e];
        row[e] = v;
        ls += v; ls2 = fmaf(v, v, ls2);
    }
    sa[tid] = ls; sb[tid] = ls2;
    __syncthreads();
    for (int o = 128; o > 0; o >>= 1) {
        if (tid < o) { sa[tid] += sa[tid + o]; sb[tid] += sb[tid + o]; }
        __syncthreads();
    }
    float m   = sa[0] * (1.0f / 1536.0f);
    float var = sb[0] * (1.0f / 1536.0f) - m * m;
    float r   = rsqrtf(var + 1e-5f);
    for (int e = tid; e < 1536; e += 256)
        out[(size_t)n * 1536 + e] = (row[e] - m) * r * lng[e] + lnb[e];
    if (tid == 0) {
        out[(size_t)NS * 1536 + n]      = 1.0f;          // mask
        out[(size_t)NS * 1536 + NS + n] = (float)idx[n]; // idx
    }
}

// ---------------------------------------------------------------------------
// Launch
// ---------------------------------------------------------------------------
extern "C" void kernel_launch(void* const* d_in, const int* in_sizes, int n_in,
                              void* d_out, int out_size)
{
    const float* wav = (const float*)d_in[0];
    const float* w0  = (const float*)d_in[1];
    const float* b0  = (const float*)d_in[2];
    const float* w1  = (const float*)d_in[3];
    const float* b1  = (const float*)d_in[4];
    const float* wr  = (const float*)d_in[5];
    const float* br  = (const float*)d_in[6];
    const float* g0  = (const float*)d_in[7];
    const float* bb0 = (const float*)d_in[8];
    const float* gr  = (const float*)d_in[9];
    const float* brr = (const float*)d_in[10];
    const float* pw  = (const float*)d_in[11];
    const float* pb  = (const float*)d_in[12];
    const float* cb  = (const float*)d_in[13];
    const float* pos = (const float*)d_in[14];
    const float* mod = (const float*)d_in[15];
    const float* lng = (const float*)d_in[16];
    const float* lnb = (const float*)d_in[17];
    float* out = (float*)d_out;

    const int B  = 8;
    int Lw = in_sizes[0] / B;           // 312000
    int L[7];
    L[0] = Lw / 5 + 1;                  // 62401
    for (int i = 1; i <= 6; i++) L[i] = L[i - 1] / 2 + 1;  // 31201..976

    float *bufA, *bufB, *mean_, *istd_, *cn_;
    int *idx_;
    cudaGetSymbolAddress((void**)&bufA,  g_bufA);
    cudaGetSymbolAddress((void**)&bufB,  g_bufB);
    cudaGetSymbolAddress((void**)&mean_, g_mean);
    cudaGetSymbolAddress((void**)&istd_, g_istd);
    cudaGetSymbolAddress((void**)&cn_,   g_cnorm);
    cudaGetSymbolAddress((void**)&idx_,  g_idx);

    // ---- layer 0: conv0 + GN(16 groups) + GELU -> bufA
    conv0_kernel<<<dim3((L[0] + 127) / 128, B), 128>>>(wav, w0, b0, bufA, Lw, L[0]);
    gn_stats<<<B * 16, 256>>>(bufA, mean_, istd_, (long long)16 * L[0]);
    norm_gelu<<<dim3((L[0] + 255) / 256, 256, B), 256>>>(bufA, mean_, istd_, g0, bb0, L[0], 16, 16);

    // ---- layer 1: conv1 (256->512, s2) + GN(32) + GELU -> bufB
    conv_gemm<10, 2, 5, false><<<dim3((L[1] + 127) / 128, 8, B), 128>>>(
        bufA, w1, b1, bufB, 256, 512, L[0], L[1]);
    gn_stats<<<B * 32, 256>>>(bufB, mean_, istd_, (long long)16 * L[1]);
    norm_gelu<<<dim3((L[1] + 255) / 256, 512, B), 256>>>(bufB, mean_, istd_, gr, brr, L[1], 32, 16);

    // ---- layers 2..6: conv_r[i] (512->512, s2) + GN(32) + GELU, ping-pong
    float* src = bufB;
    float* dst = bufA;
    for (int i = 0; i < 5; i++) {
        int Lin = L[1 + i], Lo = L[2 + i];
        conv_gemm<10, 2, 5, false><<<dim3((Lo + 127) / 128, 8, B), 128>>>(
            src, wr + (size_t)i * 512 * 512 * 10, br + i * 512, dst, 512, 512, Lin, Lo);
        gn_stats<<<B * 32, 256>>>(dst, mean_, istd_, (long long)16 * Lo);
        norm_gelu<<<dim3((Lo + 255) / 256, 512, B), 256>>>(
            dst, mean_, istd_, gr + (i + 1) * 512, brr + (i + 1) * 512, Lo, 32, 16);
        float* t = src; src = dst; dst = t;
    }
    // src now holds y6 = [8, 512, 976] (bufA); dst = bufB

    int S  = L[6];      // 976
    int NS = B * S;     // 7808

    // ---- projection: feats[b][e][l] (KW=1 conv) -> bufB
    conv_gemm<1, 1, 0, false><<<dim3((S + 127) / 128, 1536 / 64, B), 128>>>(
        src, pw, pb, dst, 512, 1536, S, S);

    // ---- VQ
    cb_norms<<<1024, 256>>>(cb, cn_);
    // scores[n][j] = f_n . c_j  -> bufA (transposed epilogue)
    conv_gemm<1, 1, 0, true><<<dim3((S + 127) / 128, 1024 / 64, B), 128>>>(
        dst, cb, nullptr, src, 1536, 1024, S, S);
    vq_argmin<<<(NS + 7) / 8, 256>>>(src, cn_, idx_, NS);

    // ---- final LN + outputs
    final_ln<<<NS, 256>>>(cb, idx_, pos, mod, lng, lnb, out, S, NS);
}

// round 8
// speedup vs baseline: 1.3076x; 1.3076x over previous
#include <cuda_runtime.h>
#include <cuda_bf16.h>
#include <math.h>
#include <stdint.h>

__device__ float          g_bufA[128000000];
__device__ float          g_bufB[16000000];
__device__ __nv_bfloat16  g_xt[384000000];
__device__ __nv_bfloat16  g_ws[43300000];
__device__ float          g_mean[512];
__device__ float          g_istd[512];
__device__ float          g_cnorm[1024];
__device__ int            g_idx[8192];

__device__ __forceinline__ float gelu_f(float x) {
    return 0.5f * x * (1.0f + erff(x * 0.7071067811865476f));
}
__device__ __forceinline__ uint32_t smem_u32(const void* p) {
    uint32_t a;
    asm("{ .reg .u64 t; cvta.to.shared.u64 t, %1; cvt.u32.u64 %0, t; }" : "=r"(a) : "l"(p));
    return a;
}
__device__ __forceinline__ void cpa16(uint32_t dst, const void* src) {
    asm volatile("cp.async.cg.shared.global [%0], [%1], 16;" :: "r"(dst), "l"(src));
}
__device__ __forceinline__ void cpa16z(uint32_t dst, const void* src, uint32_t sz) {
    asm volatile("cp.async.cg.shared.global [%0], [%1], 16, %2;" :: "r"(dst), "l"(src), "r"(sz));
}
__device__ __forceinline__ void ldmx4(uint32_t a, uint32_t* r) {
    asm volatile("ldmatrix.sync.aligned.m8n8.x4.shared.b16 {%0,%1,%2,%3}, [%4];"
                 : "=r"(r[0]), "=r"(r[1]), "=r"(r[2]), "=r"(r[3]) : "r"(a));
}
__device__ __forceinline__ void mma16816(float* c, const uint32_t* a, uint32_t b0, uint32_t b1) {
    asm volatile("mma.sync.aligned.m16n8k16.row.col.f32.bf16.bf16.f32 "
                 "{%0,%1,%2,%3}, {%4,%5,%6,%7}, {%8,%9}, {%0,%1,%2,%3};"
                 : "+f"(c[0]), "+f"(c[1]), "+f"(c[2]), "+f"(c[3])
                 : "r"(a[0]), "r"(a[1]), "r"(a[2]), "r"(a[3]), "r"(b0), "r"(b1));
}

struct f32x2 { unsigned long long u; };
__device__ __forceinline__ f32x2 pack2(float lo, float hi) {
    f32x2 r; asm("mov.b64 %0, {%1, %2};" : "=l"(r.u) : "f"(lo), "f"(hi)); return r;
}
__device__ __forceinline__ void fma2(f32x2 &d, f32x2 a, f32x2 b) {
    asm("fma.rn.f32x2 %0, %1, %2, %0;" : "+l"(d.u) : "l"(a.u), "l"(b.u));
}
__device__ __forceinline__ void unpack2(f32x2 v, float &lo, float &hi) {
    asm("mov.b64 {%0, %1}, %2;" : "=f"(lo), "=f"(hi) : "l"(v.u));
}

// conv0: Cin=1 -> yT[b][l][256]
__global__ __launch_bounds__(256)
void conv0_t(const float* __restrict__ x, const float* __restrict__ w,
             const float* __restrict__ bias, float* __restrict__ yT, int Lin, int Lout)
{
    __shared__ float Wsh[2560];
    __shared__ float Xsh[85];
    int b = blockIdx.y, l0 = blockIdx.x * 16, co = threadIdx.x;
    for (int i = co; i < 2560; i += 256) Wsh[i] = w[i];
    int g0 = 5 * l0 - 5;
    for (int i = co; i < 85; i += 256) {
        int gl = g0 + i;
        Xsh[i] = (gl >= 0 && gl < Lin) ? x[(size_t)b * Lin + gl] : 0.0f;
    }
    __syncthreads();
    float wr[10];
    #pragma unroll
    for (int t = 0; t < 10; t++) wr[t] = Wsh[co * 10 + t];
    float bv = bias[co];
    for (int j = 0; j < 16; j++) {
        int l = l0 + j;
        if (l >= Lout) break;
        float a = bv;
        #pragma unroll
        for (int t = 0; t < 10; t++) a = fmaf(wr[t], Xsh[5 * j + t], a);
        yT[((size_t)b * Lout + l) * 256 + co] = a;
    }
}

// w[512][Cin][10] fp32 -> 3 comps, layout [comp][co][t][ci]
__global__ __launch_bounds__(256)
void wprep(const float* __restrict__ w, __nv_bfloat16* __restrict__ d, int Cin)
{
    int co = blockIdx.x;
    size_t cs = (size_t)512 * 10 * Cin;
    for (int i = threadIdx.x; i < Cin * 10; i += 256) {
        int ci = i / 10, t = i - ci * 10;
        float v = w[((size_t)co * Cin + ci) * 10 + t];
        __nv_bfloat16 c0 = __float2bfloat16(v);
        float r = v - __bfloat162float(c0);
        __nv_bfloat16 c1 = __float2bfloat16(r);
        float r2 = r - __bfloat162float(c1);
        size_t o = ((size_t)co * 10 + t) * Cin + ci;
        d[o] = c0; d[cs + o] = c1; d[2 * cs + o] = __float2bfloat16(r2);
    }
}

// ---------------------------------------------------------------------------
// mma.sync conv. CTA 256thr/8 warps; tile M=128(l) x N=64(co); warp 32x32.
// K-chunk = 32 ci per tap; 3 A + 3 B comps smem, double-buffered.
// fp32 frags drained to fp64 grand every 8 chunks -> deviation ~5e-7.
// ---------------------------------------------------------------------------
#define ROWB   80
#define ACMP   10240          // 128 rows * 80B
#define BCMP   5120           // 64 rows * 80B
#define AHALF  30720          // 3 A comps
#define BUFB   46080          // A(3) + B(3)

__global__ __launch_bounds__(256)
void conv_mma(const __nv_bfloat16* __restrict__ xs, size_t planeStride,
              const __nv_bfloat16* __restrict__ ws, size_t wcs,
              const float* __restrict__ bias, float* __restrict__ yT,
              int Cin, int Cout, int Lin, int Lout)
{
    extern __shared__ __align__(128) char smem[];
    uint32_t sbase = smem_u32(smem);
    int tid = threadIdx.x, wid = tid >> 5, lane = tid & 31;
    int wm = wid & 3, wn = wid >> 2;          // 4 x 2 warp grid
    int co0 = blockIdx.x * 64;
    int l0  = blockIdx.y * 128;
    int b   = blockIdx.z;

    const __nv_bfloat16* xb = xs + (size_t)b * (size_t)Lin * Cin;
    int nkc = Cin >> 5;
    int NC  = 10 * nkc;
    const int px[6]  = {0, 1, 2, 0, 1, 0};
    const int pw_[6] = {0, 0, 0, 1, 1, 2};

    float  c[2][4][4];
    double g[2][4][4];
    #pragma unroll
    for (int i = 0; i < 2; i++)
        #pragma unroll
        for (int j = 0; j < 4; j++)
            #pragma unroll
            for (int q = 0; q < 4; q++) { c[i][j][q] = 0.0f; g[i][j][q] = 0.0; }

    #define ISSUE(kk) do {                                                            \
        int _k = (kk);                                                                \
        int _s = _k & 1, _t = _k / nkc, _ci0 = (_k - _t * nkc) << 5;                  \
        uint32_t Ab = sbase + _s * BUFB;                                              \
        uint32_t Bb = Ab + AHALF;                                                     \
        int _r0 = 2 * l0 - 5 + _t;                                                    \
        _Pragma("unroll")                                                             \
        for (int j = 0; j < 6; j++) {          /* A: 1536 segs */                     \
            int idx = tid + j * 256;                                                  \
            int comp = idx / 512, rem = idx - comp * 512;                             \
            int row = rem >> 2, seg = rem & 3;                                        \
            int r = _r0 + 2 * row;                                                    \
            int ok = (r >= 0 && r < Lin);                                             \
            const __nv_bfloat16* sa = xb + (size_t)comp * planeStride                 \
                + (size_t)(ok ? r : 0) * Cin + _ci0 + (seg << 3);                     \
            cpa16z(Ab + comp * ACMP + row * ROWB + (seg << 4), sa, ok ? 16u : 0u);    \
        }                                                                             \
        _Pragma("unroll")                                                             \
        for (int j = 0; j < 3; j++) {          /* B: 768 segs */                      \
            int idx = tid + j * 256;                                                  \
            int comp = idx >> 8, rem = idx & 255;                                     \
            int row = rem >> 2, seg = rem & 3;                                        \
            const __nv_bfloat16* sbp = ws + (size_t)comp * wcs                        \
                + ((size_t)(co0 + row) * 10 + _t) * Cin + _ci0 + (seg << 3);          \
            cpa16(Bb + comp * BCMP + row * ROWB + (seg << 4), sbp);                   \
        }                                                                             \
        asm volatile("cp.async.commit_group;" ::: "memory");                          \
    } while (0)

    ISSUE(0);
    for (int k = 0; k < NC; k++) {
        if (k + 1 < NC) {
            ISSUE(k + 1);
            asm volatile("cp.async.wait_group 1;" ::: "memory");
        } else {
            asm volatile("cp.async.wait_group 0;" ::: "memory");
        }
        __syncthreads();
        uint32_t Ab = sbase + (k & 1) * BUFB;
        uint32_t Bb = Ab + AHALF;
        uint32_t aw = Ab + (wm * 32 + (lane & 15)) * ROWB + (lane >> 4) * 16;
        uint32_t bw = Bb + (wn * 32 + ((lane >> 4) << 3) + (lane & 7)) * ROWB
                        + ((lane >> 3) & 1) * 16;
        #pragma unroll
        for (int p = 0; p < 6; p++) {
            uint32_t ac = aw + px[p]  * ACMP;
            uint32_t bc = bw + pw_[p] * BCMP;
            #pragma unroll
            for (int ks = 0; ks < 2; ks++) {
                uint32_t a[2][4], bf[2][4];
                #pragma unroll
                for (int mt = 0; mt < 2; mt++)
                    ldmx4(ac + mt * (16 * ROWB) + ks * 32, a[mt]);
                #pragma unroll
                for (int n2 = 0; n2 < 2; n2++)
                    ldmx4(bc + n2 * (16 * ROWB) + ks * 32, bf[n2]);
                #pragma unroll
                for (int mt = 0; mt < 2; mt++)
                    #pragma unroll
                    for (int nt = 0; nt < 4; nt++)
                        mma16816(c[mt][nt], a[mt],
                                 bf[nt >> 1][(nt & 1) * 2], bf[nt >> 1][(nt & 1) * 2 + 1]);
            }
        }
        if ((k & 7) == 7 || k == NC - 1) {      // drain to fp64
            #pragma unroll
            for (int mt = 0; mt < 2; mt++)
                #pragma unroll
                for (int nt = 0; nt < 4; nt++)
                    #pragma unroll
                    for (int q = 0; q < 4; q++) {
                        g[mt][nt][q] += (double)c[mt][nt][q];
                        c[mt][nt][q] = 0.0f;
                    }
        }
        __syncthreads();
    }

    #pragma unroll
    for (int mt = 0; mt < 2; mt++) {
        int lr = l0 + wm * 32 + mt * 16 + (lane >> 2);
        #pragma unroll
        for (int nt = 0; nt < 4; nt++) {
            int col = co0 + wn * 32 + nt * 8 + (lane & 3) * 2;
            float b0 = bias[col], b1 = bias[col + 1];
            if (lr < Lout) {
                float2 v = make_float2((float)g[mt][nt][0] + b0, (float)g[mt][nt][1] + b1);
                *(float2*)&yT[((size_t)b * Lout + lr) * Cout + col] = v;
            }
            if (lr + 8 < Lout) {
                float2 v = make_float2((float)g[mt][nt][2] + b0, (float)g[mt][nt][3] + b1);
                *(float2*)&yT[((size_t)b * Lout + lr + 8) * Cout + col] = v;
            }
        }
    }
}

// GN stats over [b][l][C]
__global__ __launch_bounds__(256)
void gn_stats_t(const float* __restrict__ x, float* __restrict__ mean,
                float* __restrict__ istd, int L, int C, int G)
{
    int blk = blockIdx.x, b = blk / G, g = blk % G;
    const float* p = x + (size_t)b * L * C + g * 16;
    float s = 0.0f, s2 = 0.0f;
    int tot = L * 16;
    for (int i = threadIdx.x; i < tot; i += 256) {
        int l = i >> 4, cc = i & 15;
        float v = p[(size_t)l * C + cc];
        s += v; s2 = fmaf(v, v, s2);
    }
    __shared__ float sa[256], sbm[256];
    int tid = threadIdx.x;
    sa[tid] = s; sbm[tid] = s2;
    __syncthreads();
    for (int o = 128; o > 0; o >>= 1) {
        if (tid < o) { sa[tid] += sa[tid + o]; sbm[tid] += sbm[tid + o]; }
        __syncthreads();
    }
    if (tid == 0) {
        float m = sa[0] / (float)tot;
        float var = sbm[0] / (float)tot - m * m;
        mean[blk] = m;
        istd[blk] = rsqrtf(var + 1e-5f);
    }
}

// GN apply + GELU + 3-way bf16 split -> planes
__global__ __launch_bounds__(256)
void ng_split(const float* __restrict__ x, const float* __restrict__ mean,
              const float* __restrict__ istd, const float* __restrict__ gma,
              const float* __restrict__ bta, __nv_bfloat16* __restrict__ xs,
              size_t ps, int L, int C, int G)
{
    int b = blockIdx.y;
    size_t i4 = (size_t)blockIdx.x * 256 + threadIdx.x;
    size_t n4 = (size_t)L * C >> 2;
    if (i4 >= n4) return;
    size_t base = (size_t)b * L * C;
    float4 v = ((const float4*)(x + base))[i4];
    int cc = (int)((i4 << 2) % (size_t)C);
    int bg = b * G + (cc >> 4);
    float mu = mean[bg], is = istd[bg];
    float o[4] = {v.x, v.y, v.z, v.w};
    __nv_bfloat16 p0[4], p1[4], p2[4];
    #pragma unroll
    for (int j = 0; j < 4; j++) {
        float h = gelu_f((o[j] - mu) * is * gma[cc + j] + bta[cc + j]);
        __nv_bfloat16 a = __float2bfloat16(h);
        float r = h - __bfloat162float(a);
        __nv_bfloat16 bq = __float2bfloat16(r);
        float r2 = r - __bfloat162float(bq);
        p0[j] = a; p1[j] = bq; p2[j] = __float2bfloat16(r2);
    }
    ((uint64_t*)(xs + base))[i4]          = *(uint64_t*)p0;
    ((uint64_t*)(xs + ps + base))[i4]     = *(uint64_t*)p1;
    ((uint64_t*)(xs + 2 * ps + base))[i4] = *(uint64_t*)p2;
}

__global__ __launch_bounds__(256)
void ng_inplace(float* __restrict__ x, const float* __restrict__ mean,
                const float* __restrict__ istd, const float* __restrict__ gma,
                const float* __restrict__ bta, int L, int C, int G)
{
    int b = blockIdx.y;
    size_t i4 = (size_t)blockIdx.x * 256 + threadIdx.x;
    size_t n4 = (size_t)L * C >> 2;
    if (i4 >= n4) return;
    size_t base = (size_t)b * L * C;
    float4 v = ((const float4*)(x + base))[i4];
    int cc = (int)((i4 << 2) % (size_t)C);
    int bg = b * G + (cc >> 4);
    float mu = mean[bg], is = istd[bg];
    v.x = gelu_f((v.x - mu) * is * gma[cc + 0] + bta[cc + 0]);
    v.y = gelu_f((v.y - mu) * is * gma[cc + 1] + bta[cc + 1]);
    v.z = gelu_f((v.z - mu) * is * gma[cc + 2] + bta[cc + 2]);
    v.w = gelu_f((v.w - mu) * is * gma[cc + 3] + bta[cc + 3]);
    ((float4*)(x + base))[i4] = v;
}

// SIMT f32x2 GEMM tail
__global__ __launch_bounds__(128)
void gemm_nt(const float* __restrict__ A, const float* __restrict__ B,
             const float* __restrict__ bias, float* __restrict__ out, int K, int Nj)
{
    __shared__ float As[64][17], Bs[64][17];
    int tid = threadIdx.x;
    int i0 = blockIdx.y * 64, j0 = blockIdx.x * 64;
    int isub = tid >> 4, jsub = tid & 15;
    f32x2 acc[8][2];
    #pragma unroll
    for (int i = 0; i < 8; i++) { acc[i][0].u = 0ull; acc[i][1].u = 0ull; }
    for (int k0 = 0; k0 < K; k0 += 16) {
        __syncthreads();
        for (int x = tid; x < 1024; x += 128) {
            int r = x >> 4, cc = x & 15;
            As[r][cc] = A[(size_t)(i0 + r) * K + k0 + cc];
            Bs[r][cc] = B[(size_t)(j0 + r) * K + k0 + cc];
        }
        __syncthreads();
        #pragma unroll 4
        for (int k = 0; k < 16; k++) {
            f32x2 b0 = pack2(Bs[jsub * 4 + 0][k], Bs[jsub * 4 + 1][k]);
            f32x2 b1 = pack2(Bs[jsub * 4 + 2][k], Bs[jsub * 4 + 3][k]);
            #pragma unroll
            for (int ii = 0; ii < 8; ii++) {
                float a = As[isub + (ii << 3)][k];
                f32x2 a2 = pack2(a, a);
                fma2(acc[ii][0], a2, b0);
                fma2(acc[ii][1], a2, b1);
            }
        }
    }
    int j = j0 + jsub * 4;
    float bv0 = bias ? bias[j] : 0.0f, bv1 = bias ? bias[j + 1] : 0.0f;
    float bv2 = bias ? bias[j + 2] : 0.0f, bv3 = bias ? bias[j + 3] : 0.0f;
    #pragma unroll
    for (int ii = 0; ii < 8; ii++) {
        int i = i0 + isub + (ii << 3);
        float o0, o1, o2, o3;
        unpack2(acc[ii][0], o0, o1);
        unpack2(acc[ii][1], o2, o3);
        float* p = out + (size_t)i * Nj + j;
        p[0] = o0 + bv0; p[1] = o1 + bv1; p[2] = o2 + bv2; p[3] = o3 + bv3;
    }
}

__global__ __launch_bounds__(256)
void cb_norms(const float* __restrict__ cbk, float* __restrict__ cn)
{
    const float4* row = (const float4*)(cbk + (size_t)blockIdx.x * 1536);
    float s = 0.0f;
    for (int i = threadIdx.x; i < 384; i += 256) {
        float4 v = row[i];
        s += v.x * v.x + v.y * v.y + v.z * v.z + v.w * v.w;
    }
    __shared__ float sa[256];
    int tid = threadIdx.x;
    sa[tid] = s;
    __syncthreads();
    for (int o = 128; o > 0; o >>= 1) {
        if (tid < o) sa[tid] += sa[tid + o];
        __syncthreads();
    }
    if (tid == 0) cn[blockIdx.x] = sa[0];
}

__global__ __launch_bounds__(256)
void vq_argmin(const float* __restrict__ sc, const float* __restrict__ cn,
               int* __restrict__ idx, int NS)
{
    int g = blockIdx.x * 8 + (threadIdx.x >> 5);
    int lane = threadIdx.x & 31;
    if (g >= NS) return;
    const float* s = sc + (size_t)g * 1024;
    float best = 3.4e38f; int bi = 1 << 30;
    for (int j = lane; j < 1024; j += 32) {
        float d = fmaf(-2.0f, s[j], cn[j]);
        if (d < best) { best = d; bi = j; }
    }
    #pragma unroll
    for (int o = 16; o > 0; o >>= 1) {
        float ov = __shfl_xor_sync(0xffffffffu, best, o);
        int   oi = __shfl_xor_sync(0xffffffffu, bi,   o);
        if (ov < best || (ov == best && oi < bi)) { best = ov; bi = oi; }
    }
    if (lane == 0) idx[g] = bi;
}

__global__ __launch_bounds__(256)
void final_ln(const float* __restrict__ cbk, const int* __restrict__ idx,
              const float* __restrict__ pos, const float* __restrict__ mod,
              const float* __restrict__ lng, const float* __restrict__ lnb,
              float* __restrict__ out, int S, int NS)
{
    int n = blockIdx.x, s = n % S, tid = threadIdx.x;
    __shared__ float row[1536];
    __shared__ float sa[256], sbm[256];
    const float* c = cbk + (size_t)idx[n] * 1536;
    const float* p = pos + (size_t)s * 1536;
    float ls = 0.0f, ls2 = 0.0f;
    for (int e = tid; e < 1536; e += 256) {
        float v = c[e] + p[e] + mod[e];
        row[e] = v;
        ls += v; ls2 = fmaf(v, v, ls2);
    }
    sa[tid] = ls; sbm[tid] = ls2;
    __syncthreads();
    for (int o = 128; o > 0; o >>= 1) {
        if (tid < o) { sa[tid] += sa[tid + o]; sbm[tid] += sbm[tid + o]; }
        __syncthreads();
    }
    float m = sa[0] * (1.0f / 1536.0f);
    float var = sbm[0] * (1.0f / 1536.0f) - m * m;
    float r = rsqrtf(var + 1e-5f);
    for (int e = tid; e < 1536; e += 256)
        out[(size_t)n * 1536 + e] = (row[e] - m) * r * lng[e] + lnb[e];
    if (tid == 0) {
        out[(size_t)NS * 1536 + n]      = 1.0f;
        out[(size_t)NS * 1536 + NS + n] = (float)idx[n];
    }
}

extern "C" void kernel_launch(void* const* d_in, const int* in_sizes, int n_in,
                              void* d_out, int out_size)
{
    const float* wav = (const float*)d_in[0];
    const float* w0  = (const float*)d_in[1];
    const float* b0  = (const float*)d_in[2];
    const float* w1  = (const float*)d_in[3];
    const float* b1  = (const float*)d_in[4];
    const float* wr  = (const float*)d_in[5];
    const float* br  = (const float*)d_in[6];
    const float* g0  = (const float*)d_in[7];
    const float* bb0 = (const float*)d_in[8];
    const float* gr  = (const float*)d_in[9];
    const float* brr = (const float*)d_in[10];
    const float* pw  = (const float*)d_in[11];
    const float* pb  = (const float*)d_in[12];
    const float* cbk = (const float*)d_in[13];
    const float* pos = (const float*)d_in[14];
    const float* mod = (const float*)d_in[15];
    const float* lng = (const float*)d_in[16];
    const float* lnb = (const float*)d_in[17];
    float* out = (float*)d_out;

    const int B = 8;
    int Lw = in_sizes[0] / B;
    int L[7];
    L[0] = Lw / 5 + 1;
    for (int i = 1; i <= 6; i++) L[i] = L[i - 1] / 2 + 1;

    float *bufA, *bufB, *mean_, *istd_, *cn_;
    __nv_bfloat16 *xt_, *ws_;
    int *idx_;
    cudaGetSymbolAddress((void**)&bufA,  g_bufA);
    cudaGetSymbolAddress((void**)&bufB,  g_bufB);
    cudaGetSymbolAddress((void**)&xt_,   g_xt);
    cudaGetSymbolAddress((void**)&ws_,   g_ws);
    cudaGetSymbolAddress((void**)&mean_, g_mean);
    cudaGetSymbolAddress((void**)&istd_, g_istd);
    cudaGetSymbolAddress((void**)&cn_,   g_cnorm);
    cudaGetSymbolAddress((void**)&idx_,  g_idx);

    const int SMEMSZ = 2 * BUFB;   // 92160
    cudaFuncSetAttribute(conv_mma, cudaFuncAttributeMaxDynamicSharedMemorySize, SMEMSZ);

    // split weights: layer1 (Cin=256) then 5x (Cin=512)
    wprep<<<512, 256>>>(w1, ws_, 256);
    for (int i = 0; i < 5; i++)
        wprep<<<512, 256>>>(wr + (size_t)i * 512 * 512 * 10,
                            ws_ + 3932160 + (size_t)i * 7864320, 512);

    // layer 0 (SIMT)
    conv0_t<<<dim3((L[0] + 15) / 16, B), 256>>>(wav, w0, b0, bufA, Lw, L[0]);
    gn_stats_t<<<B * 16, 256>>>(bufA, mean_, istd_, L[0], 256, 16);
    {
        size_t ps = (size_t)B * L[0] * 256;
        int nb = (int)(((size_t)L[0] * 256 / 4 + 255) / 256);
        ng_split<<<dim3(nb, B), 256>>>(bufA, mean_, istd_, g0, bb0, xt_, ps, L[0], 256, 16);
    }

    // layer 1 (MMA, Cin=256)
    conv_mma<<<dim3(8, (L[1] + 127) / 128, B), 256, SMEMSZ>>>(
        xt_, (size_t)B * L[0] * 256, ws_, 1310720, b1, bufA, 256, 512, L[0], L[1]);
    gn_stats_t<<<B * 32, 256>>>(bufA, mean_, istd_, L[1], 512, 32);
    {
        size_t ps = (size_t)B * L[1] * 512;
        int nb = (int)(((size_t)L[1] * 512 / 4 + 255) / 256);
        ng_split<<<dim3(nb, B), 256>>>(bufA, mean_, istd_, gr, brr, xt_, ps, L[1], 512, 32);
    }

    // layers 2..6 (MMA, Cin=512)
    for (int i = 0; i < 5; i++) {
        int Lin = L[1 + i], Lo = L[2 + i];
        conv_mma<<<dim3(8, (Lo + 127) / 128, B), 256, SMEMSZ>>>(
            xt_, (size_t)B * Lin * 512, ws_ + 3932160 + (size_t)i * 7864320, 2621440,
            br + i * 512, bufA, 512, 512, Lin, Lo);
        gn_stats_t<<<B * 32, 256>>>(bufA, mean_, istd_, Lo, 512, 32);
        int nb = (int)(((size_t)Lo * 512 / 4 + 255) / 256);
        if (i < 4) {
            size_t ps = (size_t)B * Lo * 512;
            ng_split<<<dim3(nb, B), 256>>>(bufA, mean_, istd_, gr + (i + 1) * 512,
                                           brr + (i + 1) * 512, xt_, ps, Lo, 512, 32);
        } else {
            ng_inplace<<<dim3(nb, B), 256>>>(bufA, mean_, istd_, gr + 5 * 512,
                                             brr + 5 * 512, Lo, 512, 32);
        }
    }

    int S = L[6];           // 976
    int NS = B * S;         // 7808

    // projection: feats[NS][1536]
    gemm_nt<<<dim3(1536 / 64, NS / 64), 128>>>(bufA, pw, pb, bufB, 512, 1536);

    // VQ
    float* sc = (float*)xt_;
    cb_norms<<<1024, 256>>>(cbk, cn_);
    gemm_nt<<<dim3(1024 / 64, NS / 64), 128>>>(bufB, cbk, nullptr, sc, 1536, 1024);
    vq_argmin<<<(NS + 7) / 8, 256>>>(sc, cn_, idx_, NS);

    final_ln<<<NS, 256>>>(cbk, idx_, pos, mod, lng, lnb, out, S, NS);
}

// round 10
// speedup vs baseline: 1.9705x; 1.5070x over previous
#include <cuda_runtime.h>
#include <cuda_fp16.h>
#include <cuda_bf16.h>
#include <math.h>
#include <stdint.h>

__device__ float          g_bufA[128000000];
__device__ float          g_bufB[16000000];
__device__ __nv_bfloat16  g_xt[384000000];    // reused as __half planes
__device__ __nv_bfloat16  g_ws[43300000];     // reused as __half split weights
__device__ float          g_mean[512];
__device__ float          g_istd[512];
__device__ float          g_cnorm[1024];
__device__ int            g_idx[8192];

__device__ __forceinline__ float gelu_f(float x) {
    return 0.5f * x * (1.0f + erff(x * 0.7071067811865476f));
}
__device__ __forceinline__ uint32_t smem_u32(const void* p) {
    uint32_t a;
    asm("{ .reg .u64 t; cvta.to.shared.u64 t, %1; cvt.u32.u64 %0, t; }" : "=r"(a) : "l"(p));
    return a;
}
__device__ __forceinline__ void cpa16(uint32_t dst, const void* src) {
    asm volatile("cp.async.cg.shared.global [%0], [%1], 16;" :: "r"(dst), "l"(src));
}
__device__ __forceinline__ void cpa16z(uint32_t dst, const void* src, uint32_t sz) {
    asm volatile("cp.async.cg.shared.global [%0], [%1], 16, %2;" :: "r"(dst), "l"(src), "r"(sz));
}
__device__ __forceinline__ void ldmx4(uint32_t a, uint32_t* r) {
    asm volatile("ldmatrix.sync.aligned.m8n8.x4.shared.b16 {%0,%1,%2,%3}, [%4];"
                 : "=r"(r[0]), "=r"(r[1]), "=r"(r[2]), "=r"(r[3]) : "r"(a));
}
__device__ __forceinline__ void mma16816(float* c, const uint32_t* a, uint32_t b0, uint32_t b1) {
    asm volatile("mma.sync.aligned.m16n8k16.row.col.f32.f16.f16.f32 "
                 "{%0,%1,%2,%3}, {%4,%5,%6,%7}, {%8,%9}, {%0,%1,%2,%3};"
                 : "+f"(c[0]), "+f"(c[1]), "+f"(c[2]), "+f"(c[3])
                 : "r"(a[0]), "r"(a[1]), "r"(a[2]), "r"(a[3]), "r"(b0), "r"(b1));
}

struct f32x2 { unsigned long long u; };
__device__ __forceinline__ f32x2 pack2(float lo, float hi) {
    f32x2 r; asm("mov.b64 %0, {%1, %2};" : "=l"(r.u) : "f"(lo), "f"(hi)); return r;
}
__device__ __forceinline__ void fma2(f32x2 &d, f32x2 a, f32x2 b) {
    asm("fma.rn.f32x2 %0, %1, %2, %0;" : "+l"(d.u) : "l"(a.u), "l"(b.u));
}
__device__ __forceinline__ void unpack2(f32x2 v, float &lo, float &hi) {
    asm("mov.b64 {%0, %1}, %2;" : "=f"(lo), "=f"(hi) : "l"(v.u));
}

// conv0: Cin=1 -> yT[b][l][256]
__global__ __launch_bounds__(256)
void conv0_t(const float* __restrict__ x, const float* __restrict__ w,
             const float* __restrict__ bias, float* __restrict__ yT, int Lin, int Lout)
{
    __shared__ float Wsh[2560];
    __shared__ float Xsh[85];
    int b = blockIdx.y, l0 = blockIdx.x * 16, co = threadIdx.x;
    for (int i = co; i < 2560; i += 256) Wsh[i] = w[i];
    int g0 = 5 * l0 - 5;
    for (int i = co; i < 85; i += 256) {
        int gl = g0 + i;
        Xsh[i] = (gl >= 0 && gl < Lin) ? x[(size_t)b * Lin + gl] : 0.0f;
    }
    __syncthreads();
    float wr[10];
    #pragma unroll
    for (int t = 0; t < 10; t++) wr[t] = Wsh[co * 10 + t];
    float bv = bias[co];
    for (int j = 0; j < 16; j++) {
        int l = l0 + j;
        if (l >= Lout) break;
        float a = bv;
        #pragma unroll
        for (int t = 0; t < 10; t++) a = fmaf(wr[t], Xsh[5 * j + t], a);
        yT[((size_t)b * Lout + l) * 256 + co] = a;
    }
}

// All 6 layers' weights -> fp16 scaled 2-comp split, layout [comp][co][t][ci]
__global__ __launch_bounds__(256)
void wprep_all(const float* __restrict__ w1, const float* __restrict__ wr,
               __half* __restrict__ d)
{
    int L = blockIdx.y, co = blockIdx.x;
    int Cin = (L == 0) ? 256 : 512;
    const float* src = (L == 0) ? w1 : wr + (size_t)(L - 1) * 512 * 512 * 10;
    __half* dst = (L == 0) ? d : d + 2621440 + (size_t)(L - 1) * 5242880;
    size_t cs = (size_t)512 * 10 * Cin;
    for (int i = threadIdx.x; i < Cin * 10; i += 256) {
        int ci = i / 10, t = i - ci * 10;
        float v = src[((size_t)co * Cin + ci) * 10 + t];
        __half c0 = __float2half(v);
        __half c1 = __float2half((v - __half2float(c0)) * 2048.0f);
        size_t o = ((size_t)co * 10 + t) * Cin + ci;
        dst[o] = c0; dst[cs + o] = c1;
    }
}

// ---------------------------------------------------------------------------
// mma.sync fp16 conv. CTA 256thr/8 warps; tile M=128(l) x N=64(co); warp 32x32.
// 2 scaled fp16 comps; products: x0w0 -> c[0], x0w1+x1w0 -> c[1];
// fp64 drain: g += c0 + c1/2048 every 8 chunks. 3-stage cp.async pipeline.
// ---------------------------------------------------------------------------
#define ROWB   80
#define ACMP   10240          // 128 rows * 80B
#define BCMP   5120           // 64 rows * 80B
#define AHALF  20480          // 2 A comps
#define BUFB   30720          // A(2) + B(2)
#define NSTG   3

__global__ __launch_bounds__(256)
void conv_mma(const __half* __restrict__ xs, size_t planeStride,
              const __half* __restrict__ ws, size_t wcs,
              const float* __restrict__ bias, float* __restrict__ yT,
              int Cin, int Cout, int Lin, int Lout)
{
    extern __shared__ __align__(128) char smem[];
    uint32_t sbase = smem_u32(smem);
    int tid = threadIdx.x, wid = tid >> 5, lane = tid & 31;
    int wm = wid & 3, wn = wid >> 2;          // 4 x 2 warp grid
    int co0 = blockIdx.x * 64;
    int l0  = blockIdx.y * 128;
    int b   = blockIdx.z;

    const __half* xb = xs + (size_t)b * (size_t)Lin * Cin;
    int nkc = Cin >> 5;
    int NC  = 10 * nkc;

    float  c[2][2][4][4];     // [accSet][mt][nt][q]
    double g[2][4][4];
    #pragma unroll
    for (int s = 0; s < 2; s++)
        #pragma unroll
        for (int i = 0; i < 2; i++)
            #pragma unroll
            for (int j = 0; j < 4; j++)
                #pragma unroll
                for (int q = 0; q < 4; q++) c[s][i][j][q] = 0.0f;
    #pragma unroll
    for (int i = 0; i < 2; i++)
        #pragma unroll
        for (int j = 0; j < 4; j++)
            #pragma unroll
            for (int q = 0; q < 4; q++) g[i][j][q] = 0.0;

    #define ISSUE(kk) do {                                                            \
        int _k = (kk);                                                                \
        int _s = _k % NSTG, _t = _k / nkc, _ci0 = (_k - _t * nkc) << 5;               \
        uint32_t Ab = sbase + _s * BUFB;                                              \
        uint32_t Bb = Ab + AHALF;                                                     \
        int _r0 = 2 * l0 - 5 + _t;                                                    \
        _Pragma("unroll")                                                             \
        for (int j = 0; j < 4; j++) {          /* A: 1024 segs */                     \
            int idx = tid + j * 256;                                                  \
            int comp = idx >> 9, rem = idx & 511;                                     \
            int row = rem >> 2, seg = rem & 3;                                        \
            int r = _r0 + 2 * row;                                                    \
            int ok = (r >= 0 && r < Lin);                                             \
            const __half* sa = xb + (size_t)comp * planeStride                        \
                + (size_t)(ok ? r : 0) * Cin + _ci0 + (seg << 3);                     \
            cpa16z(Ab + comp * ACMP + row * ROWB + (seg << 4), sa, ok ? 16u : 0u);    \
        }                                                                             \
        _Pragma("unroll")                                                             \
        for (int j = 0; j < 2; j++) {          /* B: 512 segs */                      \
            int idx = tid + j * 256;                                                  \
            int comp = idx >> 8, rem = idx & 255;                                     \
            int row = rem >> 2, seg = rem & 3;                                        \
            const __half* sbp = ws + (size_t)comp * wcs                               \
                + ((size_t)(co0 + row) * 10 + _t) * Cin + _ci0 + (seg << 3);          \
            cpa16(Bb + comp * BCMP + row * ROWB + (seg << 4), sbp);                   \
        }                                                                             \
        asm volatile("cp.async.commit_group;" ::: "memory");                          \
    } while (0)

    ISSUE(0);
    if (NC > 1) ISSUE(1);
    for (int k = 0; k < NC; k++) {
        if (k + 2 < NC) {
            ISSUE(k + 2);
            asm volatile("cp.async.wait_group 2;" ::: "memory");
        } else if (k + 1 < NC) {
            asm volatile("cp.async.wait_group 1;" ::: "memory");
        } else {
            asm volatile("cp.async.wait_group 0;" ::: "memory");
        }
        __syncthreads();
        uint32_t Ab = sbase + (k % NSTG) * BUFB;
        uint32_t Bb = Ab + AHALF;
        uint32_t aw = Ab + (wm * 32 + (lane & 15)) * ROWB + (lane >> 4) * 16;
        uint32_t bw = Bb + (wn * 32 + ((lane >> 4) << 3) + (lane & 7)) * ROWB
                        + ((lane >> 3) & 1) * 16;
        #pragma unroll
        for (int ks = 0; ks < 2; ks++) {
            uint32_t a[2][2][4], bf[2][2][4];   // [comp][mt|n2][4]
            #pragma unroll
            for (int cp = 0; cp < 2; cp++)
                #pragma unroll
                for (int mt = 0; mt < 2; mt++)
                    ldmx4(aw + cp * ACMP + mt * (16 * ROWB) + ks * 32, a[cp][mt]);
            #pragma unroll
            for (int cp = 0; cp < 2; cp++)
                #pragma unroll
                for (int n2 = 0; n2 < 2; n2++)
                    ldmx4(bw + cp * BCMP + n2 * (16 * ROWB) + ks * 32, bf[cp][n2]);
            // product 0: x0*w0 -> c[0];  products 1,2: x0*w1, x1*w0 -> c[1]
            #pragma unroll
            for (int mt = 0; mt < 2; mt++)
                #pragma unroll
                for (int nt = 0; nt < 4; nt++) {
                    uint32_t b0a = bf[0][nt >> 1][(nt & 1) * 2];
                    uint32_t b0b = bf[0][nt >> 1][(nt & 1) * 2 + 1];
                    uint32_t b1a = bf[1][nt >> 1][(nt & 1) * 2];
                    uint32_t b1b = bf[1][nt >> 1][(nt & 1) * 2 + 1];
                    mma16816(c[0][mt][nt], a[0][mt], b0a, b0b);
                    mma16816(c[1][mt][nt], a[0][mt], b1a, b1b);
                    mma16816(c[1][mt][nt], a[1][mt], b0a, b0b);
                }
        }
        if ((k & 7) == 7 || k == NC - 1) {
            #pragma unroll
            for (int mt = 0; mt < 2; mt++)
                #pragma unroll
                for (int nt = 0; nt < 4; nt++)
                    #pragma unroll
                    for (int q = 0; q < 4; q++) {
                        g[mt][nt][q] += (double)c[0][mt][nt][q]
                                      + (double)c[1][mt][nt][q] * (1.0 / 2048.0);
                        c[0][mt][nt][q] = 0.0f;
                        c[1][mt][nt][q] = 0.0f;
                    }
        }
        __syncthreads();
    }

    #pragma unroll
    for (int mt = 0; mt < 2; mt++) {
        int lr = l0 + wm * 32 + mt * 16 + (lane >> 2);
        #pragma unroll
        for (int nt = 0; nt < 4; nt++) {
            int col = co0 + wn * 32 + nt * 8 + (lane & 3) * 2;
            float b0 = bias[col], b1 = bias[col + 1];
            if (lr < Lout) {
                float2 v = make_float2((float)g[mt][nt][0] + b0, (float)g[mt][nt][1] + b1);
                *(float2*)&yT[((size_t)b * Lout + lr) * Cout + col] = v;
            }
            if (lr + 8 < Lout) {
                float2 v = make_float2((float)g[mt][nt][2] + b0, (float)g[mt][nt][3] + b1);
                *(float2*)&yT[((size_t)b * Lout + lr + 8) * Cout + col] = v;
            }
        }
    }
}

// GN stats over [b][l][C]
__global__ __launch_bounds__(256)
void gn_stats_t(const float* __restrict__ x, float* __restrict__ mean,
                float* __restrict__ istd, int L, int C, int G)
{
    int blk = blockIdx.x, b = blk / G, g = blk % G;
    const float* p = x + (size_t)b * L * C + g * 16;
    float s = 0.0f, s2 = 0.0f;
    int tot = L * 16;
    for (int i = threadIdx.x; i < tot; i += 256) {
        int l = i >> 4, cc = i & 15;
        float v = p[(size_t)l * C + cc];
        s += v; s2 = fmaf(v, v, s2);
    }
    __shared__ float sa[256], sbm[256];
    int tid = threadIdx.x;
    sa[tid] = s; sbm[tid] = s2;
    __syncthreads();
    for (int o = 128; o > 0; o >>= 1) {
        if (tid < o) { sa[tid] += sa[tid + o]; sbm[tid] += sbm[tid + o]; }
        __syncthreads();
    }
    if (tid == 0) {
        float m = sa[0] / (float)tot;
        float var = sbm[0] / (float)tot - m * m;
        mean[blk] = m;
        istd[blk] = rsqrtf(var + 1e-5f);
    }
}

// GN apply + GELU + scaled fp16 2-way split -> planes
__global__ __launch_bounds__(256)
void ng_split(const float* __restrict__ x, const float* __restrict__ mean,
              const float* __restrict__ istd, const float* __restrict__ gma,
              const float* __restrict__ bta, __half* __restrict__ xs,
              size_t ps, int L, int C, int G)
{
    int b = blockIdx.y;
    size_t i4 = (size_t)blockIdx.x * 256 + threadIdx.x;
    size_t n4 = (size_t)L * C >> 2;
    if (i4 >= n4) return;
    size_t base = (size_t)b * L * C;
    float4 v = ((const float4*)(x + base))[i4];
    int cc = (int)((i4 << 2) % (size_t)C);
    int bg = b * G + (cc >> 4);
    float mu = mean[bg], is = istd[bg];
    float o[4] = {v.x, v.y, v.z, v.w};
    __half p0[4], p1[4];
    #pragma unroll
    for (int j = 0; j < 4; j++) {
        float h = gelu_f((o[j] - mu) * is * gma[cc + j] + bta[cc + j]);
        __half a = __float2half(h);
        p0[j] = a;
        p1[j] = __float2half((h - __half2float(a)) * 2048.0f);
    }
    ((uint64_t*)(xs + base))[i4]      = *(uint64_t*)p0;
    ((uint64_t*)(xs + ps + base))[i4] = *(uint64_t*)p1;
}

__global__ __launch_bounds__(256)
void ng_inplace(float* __restrict__ x, const float* __restrict__ mean,
                const float* __restrict__ istd, const float* __restrict__ gma,
                const float* __restrict__ bta, int L, int C, int G)
{
    int b = blockIdx.y;
    size_t i4 = (size_t)blockIdx.x * 256 + threadIdx.x;
    size_t n4 = (size_t)L * C >> 2;
    if (i4 >= n4) return;
    size_t base = (size_t)b * L * C;
    float4 v = ((const float4*)(x + base))[i4];
    int cc = (int)((i4 << 2) % (size_t)C);
    int bg = b * G + (cc >> 4);
    float mu = mean[bg], is = istd[bg];
    v.x = gelu_f((v.x - mu) * is * gma[cc + 0] + bta[cc + 0]);
    v.y = gelu_f((v.y - mu) * is * gma[cc + 1] + bta[cc + 1]);
    v.z = gelu_f((v.z - mu) * is * gma[cc + 2] + bta[cc + 2]);
    v.w = gelu_f((v.w - mu) * is * gma[cc + 3] + bta[cc + 3]);
    ((float4*)(x + base))[i4] = v;
}

// SIMT f32x2 GEMM tail
__global__ __launch_bounds__(128)
void gemm_nt(const float* __restrict__ A, const float* __restrict__ B,
             const float* __restrict__ bias, float* __restrict__ out, int K, int Nj)
{
    __shared__ float As[64][17], Bs[64][17];
    int tid = threadIdx.x;
    int i0 = blockIdx.y * 64, j0 = blockIdx.x * 64;
    int isub = tid >> 4, jsub = tid & 15;
    f32x2 acc[8][2];
    #pragma unroll
    for (int i = 0; i < 8; i++) { acc[i][0].u = 0ull; acc[i][1].u = 0ull; }
    for (int k0 = 0; k0 < K; k0 += 16) {
        __syncthreads();
        for (int x = tid; x < 1024; x += 128) {
            int r = x >> 4, cc = x & 15;
            As[r][cc] = A[(size_t)(i0 + r) * K + k0 + cc];
            Bs[r][cc] = B[(size_t)(j0 + r) * K + k0 + cc];
        }
        __syncthreads();
        #pragma unroll 4
        for (int k = 0; k < 16; k++) {
            f32x2 b0 = pack2(Bs[jsub * 4 + 0][k], Bs[jsub * 4 + 1][k]);
            f32x2 b1 = pack2(Bs[jsub * 4 + 2][k], Bs[jsub * 4 + 3][k]);
            #pragma unroll
            for (int ii = 0; ii < 8; ii++) {
                float a = As[isub + (ii << 3)][k];
                f32x2 a2 = pack2(a, a);
                fma2(acc[ii][0], a2, b0);
                fma2(acc[ii][1], a2, b1);
            }
        }
    }
    int j = j0 + jsub * 4;
    float bv0 = bias ? bias[j] : 0.0f, bv1 = bias ? bias[j + 1] : 0.0f;
    float bv2 = bias ? bias[j + 2] : 0.0f, bv3 = bias ? bias[j + 3] : 0.0f;
    #pragma unroll
    for (int ii = 0; ii < 8; ii++) {
        int i = i0 + isub + (ii << 3);
        float o0, o1, o2, o3;
        unpack2(acc[ii][0], o0, o1);
        unpack2(acc[ii][1], o2, o3);
        float* p = out + (size_t)i * Nj + j;
        p[0] = o0 + bv0; p[1] = o1 + bv1; p[2] = o2 + bv2; p[3] = o3 + bv3;
    }
}

__global__ __launch_bounds__(256)
void cb_norms(const float* __restrict__ cbk, float* __restrict__ cn)
{
    const float4* row = (const float4*)(cbk + (size_t)blockIdx.x * 1536);
    float s = 0.0f;
    for (int i = threadIdx.x; i < 384; i += 256) {
        float4 v = row[i];
        s += v.x * v.x + v.y * v.y + v.z * v.z + v.w * v.w;
    }
    __shared__ float sa[256];
    int tid = threadIdx.x;
    sa[tid] = s;
    __syncthreads();
    for (int o = 128; o > 0; o >>= 1) {
        if (tid < o) sa[tid] += sa[tid + o];
        __syncthreads();
    }
    if (tid == 0) cn[blockIdx.x] = sa[0];
}

__global__ __launch_bounds__(256)
void vq_argmin(const float* __restrict__ sc, const float* __restrict__ cn,
               int* __restrict__ idx, int NS)
{
    int g = blockIdx.x * 8 + (threadIdx.x >> 5);
    int lane = threadIdx.x & 31;
    if (g >= NS) return;
    const float* s = sc + (size_t)g * 1024;
    float best = 3.4e38f; int bi = 1 << 30;
    for (int j = lane; j < 1024; j += 32) {
        float d = fmaf(-2.0f, s[j], cn[j]);
        if (d < best) { best = d; bi = j; }
    }
    #pragma unroll
    for (int o = 16; o > 0; o >>= 1) {
        float ov = __shfl_xor_sync(0xffffffffu, best, o);
        int   oi = __shfl_xor_sync(0xffffffffu, bi,   o);
        if (ov < best || (ov == best && oi < bi)) { best = ov; bi = oi; }
    }
    if (lane == 0) idx[g] = bi;
}

__global__ __launch_bounds__(256)
void final_ln(const float* __restrict__ cbk, const int* __restrict__ idx,
              const float* __restrict__ pos, const float* __restrict__ mod,
              const float* __restrict__ lng, const float* __restrict__ lnb,
              float* __restrict__ out, int S, int NS)
{
    int n = blockIdx.x, s = n % S, tid = threadIdx.x;
    __shared__ float row[1536];
    __shared__ float sa[256], sbm[256];
    const float* c = cbk + (size_t)idx[n] * 1536;
    const float* p = pos + (size_t)s * 1536;
    float ls = 0.0f, ls2 = 0.0f;
    for (int e = tid; e < 1536; e += 256) {
        float v = c[e] + p[e] + mod[e];
        row[e] = v;
        ls += v; ls2 = fmaf(v, v, ls2);
    }
    sa[tid] = ls; sbm[tid] = ls2;
    __syncthreads();
    for (int o = 128; o > 0; o >>= 1) {
        if (tid < o) { sa[tid] += sa[tid + o]; sbm[tid] += sbm[tid + o]; }
        __syncthreads();
    }
    float m = sa[0] * (1.0f / 1536.0f);
    float var = sbm[0] * (1.0f / 1536.0f) - m * m;
    float r = rsqrtf(var + 1e-5f);
    for (int e = tid; e < 1536; e += 256)
        out[(size_t)n * 1536 + e] = (row[e] - m) * r * lng[e] + lnb[e];
    if (tid == 0) {
        out[(size_t)NS * 1536 + n]      = 1.0f;
        out[(size_t)NS * 1536 + NS + n] = (float)idx[n];
    }
}

extern "C" void kernel_launch(void* const* d_in, const int* in_sizes, int n_in,
                              void* d_out, int out_size)
{
    const float* wav = (const float*)d_in[0];
    const float* w0  = (const float*)d_in[1];
    const float* b0  = (const float*)d_in[2];
    const float* w1  = (const float*)d_in[3];
    const float* b1  = (const float*)d_in[4];
    const float* wr  = (const float*)d_in[5];
    const float* br  = (const float*)d_in[6];
    const float* g0  = (const float*)d_in[7];
    const float* bb0 = (const float*)d_in[8];
    const float* gr  = (const float*)d_in[9];
    const float* brr = (const float*)d_in[10];
    const float* pw  = (const float*)d_in[11];
    const float* pb  = (const float*)d_in[12];
    const float* cbk = (const float*)d_in[13];
    const float* pos = (const float*)d_in[14];
    const float* mod = (const float*)d_in[15];
    const float* lng = (const float*)d_in[16];
    const float* lnb = (const float*)d_in[17];
    float* out = (float*)d_out;

    const int B = 8;
    int Lw = in_sizes[0] / B;
    int L[7];
    L[0] = Lw / 5 + 1;
    for (int i = 1; i <= 6; i++) L[i] = L[i - 1] / 2 + 1;

    float *bufA, *bufB, *mean_, *istd_, *cn_;
    __half *xt_, *ws_;
    int *idx_;
    cudaGetSymbolAddress((void**)&bufA,  g_bufA);
    cudaGetSymbolAddress((void**)&bufB,  g_bufB);
    cudaGetSymbolAddress((void**)&xt_,   g_xt);
    cudaGetSymbolAddress((void**)&ws_,   g_ws);
    cudaGetSymbolAddress((void**)&mean_, g_mean);
    cudaGetSymbolAddress((void**)&istd_, g_istd);
    cudaGetSymbolAddress((void**)&cn_,   g_cnorm);
    cudaGetSymbolAddress((void**)&idx_,  g_idx);

    const int SMEMSZ = NSTG * BUFB;   // 92160
    cudaFuncSetAttribute(conv_mma, cudaFuncAttributeMaxDynamicSharedMemorySize, SMEMSZ);

    // launch order: 0 cb_norms, 1 wprep_all, 2 conv0, 3 gn, 4 split, 5 conv_mma
    cb_norms<<<1024, 256>>>(cbk, cn_);
    wprep_all<<<dim3(512, 6), 256>>>(w1, wr, ws_);

    conv0_t<<<dim3((L[0] + 15) / 16, B), 256>>>(wav, w0, b0, bufA, Lw, L[0]);
    gn_stats_t<<<B * 16, 256>>>(bufA, mean_, istd_, L[0], 256, 16);
    {
        size_t ps = (size_t)B * L[0] * 256;
        int nb = (int)(((size_t)L[0] * 256 / 4 + 255) / 256);
        ng_split<<<dim3(nb, B), 256>>>(bufA, mean_, istd_, g0, bb0, xt_, ps, L[0], 256, 16);
    }

    // layer 1 (MMA, Cin=256)
    conv_mma<<<dim3(8, (L[1] + 127) / 128, B), 256, SMEMSZ>>>(
        xt_, (size_t)B * L[0] * 256, ws_, 1310720, b1, bufA, 256, 512, L[0], L[1]);
    gn_stats_t<<<B * 32, 256>>>(bufA, mean_, istd_, L[1], 512, 32);
    {
        size_t ps = (size_t)B * L[1] * 512;
        int nb = (int)(((size_t)L[1] * 512 / 4 + 255) / 256);
        ng_split<<<dim3(nb, B), 256>>>(bufA, mean_, istd_, gr, brr, xt_, ps, L[1], 512, 32);
    }

    // layers 2..6 (MMA, Cin=512)
    for (int i = 0; i < 5; i++) {
        int Lin = L[1 + i], Lo = L[2 + i];
        conv_mma<<<dim3(8, (Lo + 127) / 128, B), 256, SMEMSZ>>>(
            xt_, (size_t)B * Lin * 512, ws_ + 2621440 + (size_t)i * 5242880, 2621440,
            br + i * 512, bufA, 512, 512, Lin, Lo);
        gn_stats_t<<<B * 32, 256>>>(bufA, mean_, istd_, Lo, 512, 32);
        int nb = (int)(((size_t)Lo * 512 / 4 + 255) / 256);
        if (i < 4) {
            size_t ps = (size_t)B * Lo * 512;
            ng_split<<<dim3(nb, B), 256>>>(bufA, mean_, istd_, gr + (i + 1) * 512,
                                           brr + (i + 1) * 512, xt_, ps, Lo, 512, 32);
        } else {
            ng_inplace<<<dim3(nb, B), 256>>>(bufA, mean_, istd_, gr + 5 * 512,
                                             brr + 5 * 512, Lo, 512, 32);
        }
    }

    int S = L[6];           // 976
    int NS = B * S;         // 7808

    // projection: feats[NS][1536]
    gemm_nt<<<dim3(1536 / 64, NS / 64), 128>>>(bufA, pw, pb, bufB, 512, 1536);

    // VQ
    float* sc = (float*)xt_;
    gemm_nt<<<dim3(1024 / 64, NS / 64), 128>>>(bufB, cbk, nullptr, sc, 1536, 1024);
    vq_argmin<<<(NS + 7) / 8, 256>>>(sc, cn_, idx_, NS);

    final_ln<<<NS, 256>>>(cbk, idx_, pos, mod, lng, lnb, out, S, NS);
}

// round 12
// speedup vs baseline: 2.3002x; 1.1673x over previous
#include <cuda_runtime.h>
#include <cuda_fp16.h>
#include <cuda_bf16.h>
#include <math.h>
#include <stdint.h>

__device__ float          g_bufA[128000000];
__device__ float          g_bufB[16000000];
__device__ __nv_bfloat16  g_xt[384000000];    // reused as __half planes
__device__ __nv_bfloat16  g_ws[43300000];     // reused as __half split weights
__device__ float          g_mean[512];
__device__ float          g_istd[512];
__device__ float          g_cnorm[1024];
__device__ int            g_idx[8192];

__device__ __forceinline__ float gelu_f(float x) {
    return 0.5f * x * (1.0f + erff(x * 0.7071067811865476f));
}
__device__ __forceinline__ uint32_t smem_u32(const void* p) {
    uint32_t a;
    asm("{ .reg .u64 t; cvta.to.shared.u64 t, %1; cvt.u32.u64 %0, t; }" : "=r"(a) : "l"(p));
    return a;
}
__device__ __forceinline__ void cpa16(uint32_t dst, const void* src) {
    asm volatile("cp.async.cg.shared.global [%0], [%1], 16;" :: "r"(dst), "l"(src));
}
__device__ __forceinline__ void cpa16z(uint32_t dst, const void* src, uint32_t sz) {
    asm volatile("cp.async.cg.shared.global [%0], [%1], 16, %2;" :: "r"(dst), "l"(src), "r"(sz));
}
__device__ __forceinline__ void ldmx4(uint32_t a, uint32_t* r) {
    asm volatile("ldmatrix.sync.aligned.m8n8.x4.shared.b16 {%0,%1,%2,%3}, [%4];"
                 : "=r"(r[0]), "=r"(r[1]), "=r"(r[2]), "=r"(r[3]) : "r"(a));
}
__device__ __forceinline__ void mma16816(float* c, const uint32_t* a, uint32_t b0, uint32_t b1) {
    asm volatile("mma.sync.aligned.m16n8k16.row.col.f32.f16.f16.f32 "
                 "{%0,%1,%2,%3}, {%4,%5,%6,%7}, {%8,%9}, {%0,%1,%2,%3};"
                 : "+f"(c[0]), "+f"(c[1]), "+f"(c[2]), "+f"(c[3])
                 : "r"(a[0]), "r"(a[1]), "r"(a[2]), "r"(a[3]), "r"(b0), "r"(b1));
}

struct f32x2 { unsigned long long u; };
__device__ __forceinline__ f32x2 pack2(float lo, float hi) {
    f32x2 r; asm("mov.b64 %0, {%1, %2};" : "=l"(r.u) : "f"(lo), "f"(hi)); return r;
}
__device__ __forceinline__ void fma2(f32x2 &d, f32x2 a, f32x2 b) {
    asm("fma.rn.f32x2 %0, %1, %2, %0;" : "+l"(d.u) : "l"(a.u), "l"(b.u));
}
__device__ __forceinline__ void unpack2(f32x2 v, float &lo, float &hi) {
    asm("mov.b64 {%0, %1}, %2;" : "=f"(lo), "=f"(hi) : "l"(v.u));
}

// conv0: Cin=1 -> yT[b][l][256]
__global__ __launch_bounds__(256)
void conv0_t(const float* __restrict__ x, const float* __restrict__ w,
             const float* __restrict__ bias, float* __restrict__ yT, int Lin, int Lout)
{
    __shared__ float Wsh[2560];
    __shared__ float Xsh[85];
    int b = blockIdx.y, l0 = blockIdx.x * 16, co = threadIdx.x;
    for (int i = co; i < 2560; i += 256) Wsh[i] = w[i];
    int g0 = 5 * l0 - 5;
    for (int i = co; i < 85; i += 256) {
        int gl = g0 + i;
        Xsh[i] = (gl >= 0 && gl < Lin) ? x[(size_t)b * Lin + gl] : 0.0f;
    }
    __syncthreads();
    float wr[10];
    #pragma unroll
    for (int t = 0; t < 10; t++) wr[t] = Wsh[co * 10 + t];
    float bv = bias[co];
    for (int j = 0; j < 16; j++) {
        int l = l0 + j;
        if (l >= Lout) break;
        float a = bv;
        #pragma unroll
        for (int t = 0; t < 10; t++) a = fmaf(wr[t], Xsh[5 * j + t], a);
        yT[((size_t)b * Lout + l) * 256 + co] = a;
    }
}

// All 6 layers' weights -> fp16 scaled 2-comp split, layout [comp][co][t][ci]
__global__ __launch_bounds__(256)
void wprep_all(const float* __restrict__ w1, const float* __restrict__ wr,
               __half* __restrict__ d)
{
    int L = blockIdx.y, co = blockIdx.x;
    int Cin = (L == 0) ? 256 : 512;
    const float* src = (L == 0) ? w1 : wr + (size_t)(L - 1) * 512 * 512 * 10;
    __half* dst = (L == 0) ? d : d + 2621440 + (size_t)(L - 1) * 5242880;
    size_t cs = (size_t)512 * 10 * Cin;
    for (int i = threadIdx.x; i < Cin * 10; i += 256) {
        int ci = i / 10, t = i - ci * 10;
        float v = src[((size_t)co * Cin + ci) * 10 + t];
        __half c0 = __float2half(v);
        __half c1 = __float2half((v - __half2float(c0)) * 2048.0f);
        size_t o = ((size_t)co * 10 + t) * Cin + ci;
        dst[o] = c0; dst[cs + o] = c1;
    }
}

// ---------------------------------------------------------------------------
// mma.sync fp16 conv. CTA 256thr/8 warps; tile M=128(l) x N=64(co); warp 32x32.
// K-chunk = 64 ci per tap (4 k16 steps); 2 scaled fp16 comps;
// products: x0w0 -> c[0], x0w1+x1w0 -> c[1]; fp64 drain g += c0 + c1/2048
// every 4 chunks (256 K-adds per group). 2-stage cp.async pipeline.
// ---------------------------------------------------------------------------
#define ROWB   144            // 128B data + 16B pad (conflict-free ldmatrix)
#define ACMP   18432          // 128 rows * 144B
#define BCMP   9216           // 64 rows * 144B
#define AHALF  36864          // 2 A comps
#define BUFB   55296          // A(2) + B(2)
#define NSTG   2

__global__ __launch_bounds__(256)
void conv_mma(const __half* __restrict__ xs, size_t planeStride,
              const __half* __restrict__ ws, size_t wcs,
              const float* __restrict__ bias, float* __restrict__ yT,
              int Cin, int Cout, int Lin, int Lout)
{
    extern __shared__ __align__(128) char smem[];
    uint32_t sbase = smem_u32(smem);
    int tid = threadIdx.x, wid = tid >> 5, lane = tid & 31;
    int wm = wid & 3, wn = wid >> 2;          // 4 x 2 warp grid
    int co0 = blockIdx.x * 64;
    int l0  = blockIdx.y * 128;
    int b   = blockIdx.z;

    const __half* xb = xs + (size_t)b * (size_t)Lin * Cin;
    int nkc = Cin >> 6;                        // ci chunks of 64
    int NC  = 10 * nkc;

    float  c[2][2][4][4];     // [accSet][mt][nt][q]
    double g[2][4][4];
    #pragma unroll
    for (int s = 0; s < 2; s++)
        #pragma unroll
        for (int i = 0; i < 2; i++)
            #pragma unroll
            for (int j = 0; j < 4; j++)
                #pragma unroll
                for (int q = 0; q < 4; q++) c[s][i][j][q] = 0.0f;
    #pragma unroll
    for (int i = 0; i < 2; i++)
        #pragma unroll
        for (int j = 0; j < 4; j++)
            #pragma unroll
            for (int q = 0; q < 4; q++) g[i][j][q] = 0.0;

    #define ISSUE(kk) do {                                                            \
        int _k = (kk);                                                                \
        int _s = _k % NSTG, _t = _k / nkc, _ci0 = (_k - _t * nkc) << 6;               \
        uint32_t Ab = sbase + _s * BUFB;                                              \
        uint32_t Bb = Ab + AHALF;                                                     \
        int _r0 = 2 * l0 - 5 + _t;                                                    \
        _Pragma("unroll")                                                             \
        for (int j = 0; j < 8; j++) {          /* A: 2048 segs */                     \
            int idx = tid + j * 256;                                                  \
            int comp = idx >> 10, rem = idx & 1023;                                   \
            int row = rem >> 3, seg = rem & 7;                                        \
            int r = _r0 + 2 * row;                                                    \
            int ok = (r >= 0 && r < Lin);                                             \
            const __half* sa = xb + (size_t)comp * planeStride                        \
                + (size_t)(ok ? r : 0) * Cin + _ci0 + (seg << 3);                     \
            cpa16z(Ab + comp * ACMP + row * ROWB + (seg << 4), sa, ok ? 16u : 0u);    \
        }                                                                             \
        _Pragma("unroll")                                                             \
        for (int j = 0; j < 4; j++) {          /* B: 1024 segs */                     \
            int idx = tid + j * 256;                                                  \
            int comp = idx >> 9, rem = idx & 511;                                     \
            int row = rem >> 3, seg = rem & 7;                                        \
            const __half* sbp = ws + (size_t)comp * wcs                               \
                + ((size_t)(co0 + row) * 10 + _t) * Cin + _ci0 + (seg << 3);          \
            cpa16(Bb + comp * BCMP + row * ROWB + (seg << 4), sbp);                   \
        }                                                                             \
        asm volatile("cp.async.commit_group;" ::: "memory");                          \
    } while (0)

    ISSUE(0);
    for (int k = 0; k < NC; k++) {
        if (k + 1 < NC) {
            ISSUE(k + 1);
            asm volatile("cp.async.wait_group 1;" ::: "memory");
        } else {
            asm volatile("cp.async.wait_group 0;" ::: "memory");
        }
        __syncthreads();
        uint32_t Ab = sbase + (k % NSTG) * BUFB;
        uint32_t Bb = Ab + AHALF;
        uint32_t aw = Ab + (wm * 32 + (lane & 15)) * ROWB + (lane >> 4) * 16;
        uint32_t bw = Bb + (wn * 32 + ((lane >> 4) << 3) + (lane & 7)) * ROWB
                        + ((lane >> 3) & 1) * 16;
        #pragma unroll
        for (int ks = 0; ks < 4; ks++) {
            uint32_t a[2][2][4], bf[2][2][4];   // [comp][mt|n2][4]
            #pragma unroll
            for (int cp = 0; cp < 2; cp++)
                #pragma unroll
                for (int mt = 0; mt < 2; mt++)
                    ldmx4(aw + cp * ACMP + mt * (16 * ROWB) + ks * 32, a[cp][mt]);
            #pragma unroll
            for (int cp = 0; cp < 2; cp++)
                #pragma unroll
                for (int n2 = 0; n2 < 2; n2++)
                    ldmx4(bw + cp * BCMP + n2 * (16 * ROWB) + ks * 32, bf[cp][n2]);
            // product 0: x0*w0 -> c[0];  products 1,2: x0*w1, x1*w0 -> c[1]
            #pragma unroll
            for (int mt = 0; mt < 2; mt++)
                #pragma unroll
                for (int nt = 0; nt < 4; nt++) {
                    uint32_t b0a = bf[0][nt >> 1][(nt & 1) * 2];
                    uint32_t b0b = bf[0][nt >> 1][(nt & 1) * 2 + 1];
                    uint32_t b1a = bf[1][nt >> 1][(nt & 1) * 2];
                    uint32_t b1b = bf[1][nt >> 1][(nt & 1) * 2 + 1];
                    mma16816(c[0][mt][nt], a[0][mt], b0a, b0b);
                    mma16816(c[1][mt][nt], a[0][mt], b1a, b1b);
                    mma16816(c[1][mt][nt], a[1][mt], b0a, b0b);
                }
        }
        if ((k & 3) == 3 || k == NC - 1) {
            #pragma unroll
            for (int mt = 0; mt < 2; mt++)
                #pragma unroll
                for (int nt = 0; nt < 4; nt++)
                    #pragma unroll
                    for (int q = 0; q < 4; q++) {
                        g[mt][nt][q] += (double)c[0][mt][nt][q]
                                      + (double)c[1][mt][nt][q] * (1.0 / 2048.0);
                        c[0][mt][nt][q] = 0.0f;
                        c[1][mt][nt][q] = 0.0f;
                    }
        }
        __syncthreads();
    }

    #pragma unroll
    for (int mt = 0; mt < 2; mt++) {
        int lr = l0 + wm * 32 + mt * 16 + (lane >> 2);
        #pragma unroll
        for (int nt = 0; nt < 4; nt++) {
            int col = co0 + wn * 32 + nt * 8 + (lane & 3) * 2;
            float b0 = bias[col], b1 = bias[col + 1];
            if (lr < Lout) {
                float2 v = make_float2((float)g[mt][nt][0] + b0, (float)g[mt][nt][1] + b1);
                *(float2*)&yT[((size_t)b * Lout + lr) * Cout + col] = v;
            }
            if (lr + 8 < Lout) {
                float2 v = make_float2((float)g[mt][nt][2] + b0, (float)g[mt][nt][3] + b1);
                *(float2*)&yT[((size_t)b * Lout + lr + 8) * Cout + col] = v;
            }
        }
    }
}

// GN stats over [b][l][C]
__global__ __launch_bounds__(256)
void gn_stats_t(const float* __restrict__ x, float* __restrict__ mean,
                float* __restrict__ istd, int L, int C, int G)
{
    int blk = blockIdx.x, b = blk / G, g = blk % G;
    const float* p = x + (size_t)b * L * C + g * 16;
    float s = 0.0f, s2 = 0.0f;
    int tot = L * 16;
    for (int i = threadIdx.x; i < tot; i += 256) {
        int l = i >> 4, cc = i & 15;
        float v = p[(size_t)l * C + cc];
        s += v; s2 = fmaf(v, v, s2);
    }
    __shared__ float sa[256], sbm[256];
    int tid = threadIdx.x;
    sa[tid] = s; sbm[tid] = s2;
    __syncthreads();
    for (int o = 128; o > 0; o >>= 1) {
        if (tid < o) { sa[tid] += sa[tid + o]; sbm[tid] += sbm[tid + o]; }
        __syncthreads();
    }
    if (tid == 0) {
        float m = sa[0] / (float)tot;
        float var = sbm[0] / (float)tot - m * m;
        mean[blk] = m;
        istd[blk] = rsqrtf(var + 1e-5f);
    }
}

// GN apply + GELU + scaled fp16 2-way split -> planes
__global__ __launch_bounds__(256)
void ng_split(const float* __restrict__ x, const float* __restrict__ mean,
              const float* __restrict__ istd, const float* __restrict__ gma,
              const float* __restrict__ bta, __half* __restrict__ xs,
              size_t ps, int L, int C, int G)
{
    int b = blockIdx.y;
    size_t i4 = (size_t)blockIdx.x * 256 + threadIdx.x;
    size_t n4 = (size_t)L * C >> 2;
    if (i4 >= n4) return;
    size_t base = (size_t)b * L * C;
    float4 v = ((const float4*)(x + base))[i4];
    int cc = (int)((i4 << 2) % (size_t)C);
    int bg = b * G + (cc >> 4);
    float mu = mean[bg], is = istd[bg];
    float o[4] = {v.x, v.y, v.z, v.w};
    __half p0[4], p1[4];
    #pragma unroll
    for (int j = 0; j < 4; j++) {
        float h = gelu_f((o[j] - mu) * is * gma[cc + j] + bta[cc + j]);
        __half a = __float2half(h);
        p0[j] = a;
        p1[j] = __float2half((h - __half2float(a)) * 2048.0f);
    }
    ((uint64_t*)(xs + base))[i4]      = *(uint64_t*)p0;
    ((uint64_t*)(xs + ps + base))[i4] = *(uint64_t*)p1;
}

__global__ __launch_bounds__(256)
void ng_inplace(float* __restrict__ x, const float* __restrict__ mean,
                const float* __restrict__ istd, const float* __restrict__ gma,
                const float* __restrict__ bta, int L, int C, int G)
{
    int b = blockIdx.y;
    size_t i4 = (size_t)blockIdx.x * 256 + threadIdx.x;
    size_t n4 = (size_t)L * C >> 2;
    if (i4 >= n4) return;
    size_t base = (size_t)b * L * C;
    float4 v = ((const float4*)(x + base))[i4];
    int cc = (int)((i4 << 2) % (size_t)C);
    int bg = b * G + (cc >> 4);
    float mu = mean[bg], is = istd[bg];
    v.x = gelu_f((v.x - mu) * is * gma[cc + 0] + bta[cc + 0]);
    v.y = gelu_f((v.y - mu) * is * gma[cc + 1] + bta[cc + 1]);
    v.z = gelu_f((v.z - mu) * is * gma[cc + 2] + bta[cc + 2]);
    v.w = gelu_f((v.w - mu) * is * gma[cc + 3] + bta[cc + 3]);
    ((float4*)(x + base))[i4] = v;
}

// SIMT f32x2 GEMM tail
__global__ __launch_bounds__(128)
void gemm_nt(const float* __restrict__ A, const float* __restrict__ B,
             const float* __restrict__ bias, float* __restrict__ out, int K, int Nj)
{
    __shared__ float As[64][17], Bs[64][17];
    int tid = threadIdx.x;
    int i0 = blockIdx.y * 64, j0 = blockIdx.x * 64;
    int isub = tid >> 4, jsub = tid & 15;
    f32x2 acc[8][2];
    #pragma unroll
    for (int i = 0; i < 8; i++) { acc[i][0].u = 0ull; acc[i][1].u = 0ull; }
    for (int k0 = 0; k0 < K; k0 += 16) {
        __syncthreads();
        for (int x = tid; x < 1024; x += 128) {
            int r = x >> 4, cc = x & 15;
            As[r][cc] = A[(size_t)(i0 + r) * K + k0 + cc];
            Bs[r][cc] = B[(size_t)(j0 + r) * K + k0 + cc];
        }
        __syncthreads();
        #pragma unroll 4
        for (int k = 0; k < 16; k++) {
            f32x2 b0 = pack2(Bs[jsub * 4 + 0][k], Bs[jsub * 4 + 1][k]);
            f32x2 b1 = pack2(Bs[jsub * 4 + 2][k], Bs[jsub * 4 + 3][k]);
            #pragma unroll
            for (int ii = 0; ii < 8; ii++) {
                float a = As[isub + (ii << 3)][k];
                f32x2 a2 = pack2(a, a);
                fma2(acc[ii][0], a2, b0);
                fma2(acc[ii][1], a2, b1);
            }
        }
    }
    int j = j0 + jsub * 4;
    float bv0 = bias ? bias[j] : 0.0f, bv1 = bias ? bias[j + 1] : 0.0f;
    float bv2 = bias ? bias[j + 2] : 0.0f, bv3 = bias ? bias[j + 3] : 0.0f;
    #pragma unroll
    for (int ii = 0; ii < 8; ii++) {
        int i = i0 + isub + (ii << 3);
        float o0, o1, o2, o3;
        unpack2(acc[ii][0], o0, o1);
        unpack2(acc[ii][1], o2, o3);
        float* p = out + (size_t)i * Nj + j;
        p[0] = o0 + bv0; p[1] = o1 + bv1; p[2] = o2 + bv2; p[3] = o3 + bv3;
    }
}

__global__ __launch_bounds__(256)
void cb_norms(const float* __restrict__ cbk, float* __restrict__ cn)
{
    const float4* row = (const float4*)(cbk + (size_t)blockIdx.x * 1536);
    float s = 0.0f;
    for (int i = threadIdx.x; i < 384; i += 256) {
        float4 v = row[i];
        s += v.x * v.x + v.y * v.y + v.z * v.z + v.w * v.w;
    }
    __shared__ float sa[256];
    int tid = threadIdx.x;
    sa[tid] = s;
    __syncthreads();
    for (int o = 128; o > 0; o >>= 1) {
        if (tid < o) sa[tid] += sa[tid + o];
        __syncthreads();
    }
    if (tid == 0) cn[blockIdx.x] = sa[0];
}

__global__ __launch_bounds__(256)
void vq_argmin(const float* __restrict__ sc, const float* __restrict__ cn,
               int* __restrict__ idx, int NS)
{
    int g = blockIdx.x * 8 + (threadIdx.x >> 5);
    int lane = threadIdx.x & 31;
    if (g >= NS) return;
    const float* s = sc + (size_t)g * 1024;
    float best = 3.4e38f; int bi = 1 << 30;
    for (int j = lane; j < 1024; j += 32) {
        float d = fmaf(-2.0f, s[j], cn[j]);
        if (d < best) { best = d; bi = j; }
    }
    #pragma unroll
    for (int o = 16; o > 0; o >>= 1) {
        float ov = __shfl_xor_sync(0xffffffffu, best, o);
        int   oi = __shfl_xor_sync(0xffffffffu, bi,   o);
        if (ov < best || (ov == best && oi < bi)) { best = ov; bi = oi; }
    }
    if (lane == 0) idx[g] = bi;
}

__global__ __launch_bounds__(256)
void final_ln(const float* __restrict__ cbk, const int* __restrict__ idx,
              const float* __restrict__ pos, const float* __restrict__ mod,
              const float* __restrict__ lng, const float* __restrict__ lnb,
              float* __restrict__ out, int S, int NS)
{
    int n = blockIdx.x, s = n % S, tid = threadIdx.x;
    __shared__ float row[1536];
    __shared__ float sa[256], sbm[256];
    const float* c = cbk + (size_t)idx[n] * 1536;
    const float* p = pos + (size_t)s * 1536;
    float ls = 0.0f, ls2 = 0.0f;
    for (int e = tid; e < 1536; e += 256) {
        float v = c[e] + p[e] + mod[e];
        row[e] = v;
        ls += v; ls2 = fmaf(v, v, ls2);
    }
    sa[tid] = ls; sbm[tid] = ls2;
    __syncthreads();
    for (int o = 128; o > 0; o >>= 1) {
        if (tid < o) { sa[tid] += sa[tid + o]; sbm[tid] += sbm[tid + o]; }
        __syncthreads();
    }
    float m = sa[0] * (1.0f / 1536.0f);
    float var = sbm[0] * (1.0f / 1536.0f) - m * m;
    float r = rsqrtf(var + 1e-5f);
    for (int e = tid; e < 1536; e += 256)
        out[(size_t)n * 1536 + e] = (row[e] - m) * r * lng[e] + lnb[e];
    if (tid == 0) {
        out[(size_t)NS * 1536 + n]      = 1.0f;
        out[(size_t)NS * 1536 + NS + n] = (float)idx[n];
    }
}

extern "C" void kernel_launch(void* const* d_in, const int* in_sizes, int n_in,
                              void* d_out, int out_size)
{
    const float* wav = (const float*)d_in[0];
    const float* w0  = (const float*)d_in[1];
    const float* b0  = (const float*)d_in[2];
    const float* w1  = (const float*)d_in[3];
    const float* b1  = (const float*)d_in[4];
    const float* wr  = (const float*)d_in[5];
    const float* br  = (const float*)d_in[6];
    const float* g0  = (const float*)d_in[7];
    const float* bb0 = (const float*)d_in[8];
    const float* gr  = (const float*)d_in[9];
    const float* brr = (const float*)d_in[10];
    const float* pw  = (const float*)d_in[11];
    const float* pb  = (const float*)d_in[12];
    const float* cbk = (const float*)d_in[13];
    const float* pos = (const float*)d_in[14];
    const float* mod = (const float*)d_in[15];
    const float* lng = (const float*)d_in[16];
    const float* lnb = (const float*)d_in[17];
    float* out = (float*)d_out;

    const int B = 8;
    int Lw = in_sizes[0] / B;
    int L[7];
    L[0] = Lw / 5 + 1;
    for (int i = 1; i <= 6; i++) L[i] = L[i - 1] / 2 + 1;

    float *bufA, *bufB, *mean_, *istd_, *cn_;
    __half *xt_, *ws_;
    int *idx_;
    cudaGetSymbolAddress((void**)&bufA,  g_bufA);
    cudaGetSymbolAddress((void**)&bufB,  g_bufB);
    cudaGetSymbolAddress((void**)&xt_,   g_xt);
    cudaGetSymbolAddress((void**)&ws_,   g_ws);
    cudaGetSymbolAddress((void**)&mean_, g_mean);
    cudaGetSymbolAddress((void**)&istd_, g_istd);
    cudaGetSymbolAddress((void**)&cn_,   g_cnorm);
    cudaGetSymbolAddress((void**)&idx_,  g_idx);

    const int SMEMSZ = NSTG * BUFB;   // 110592
    cudaFuncSetAttribute(conv_mma, cudaFuncAttributeMaxDynamicSharedMemorySize, SMEMSZ);

    cb_norms<<<1024, 256>>>(cbk, cn_);
    wprep_all<<<dim3(512, 6), 256>>>(w1, wr, ws_);

    conv0_t<<<dim3((L[0] + 15) / 16, B), 256>>>(wav, w0, b0, bufA, Lw, L[0]);
    gn_stats_t<<<B * 16, 256>>>(bufA, mean_, istd_, L[0], 256, 16);
    {
        size_t ps = (size_t)B * L[0] * 256;
        int nb = (int)(((size_t)L[0] * 256 / 4 + 255) / 256);
        ng_split<<<dim3(nb, B), 256>>>(bufA, mean_, istd_, g0, bb0, xt_, ps, L[0], 256, 16);
    }

    // layer 1 (MMA, Cin=256)
    conv_mma<<<dim3(8, (L[1] + 127) / 128, B), 256, SMEMSZ>>>(
        xt_, (size_t)B * L[0] * 256, ws_, 1310720, b1, bufA, 256, 512, L[0], L[1]);
    gn_stats_t<<<B * 32, 256>>>(bufA, mean_, istd_, L[1], 512, 32);
    {
        size_t ps = (size_t)B * L[1] * 512;
        int nb = (int)(((size_t)L[1] * 512 / 4 + 255) / 256);
        ng_split<<<dim3(nb, B), 256>>>(bufA, mean_, istd_, gr, brr, xt_, ps, L[1], 512, 32);
    }

    // layers 2..6 (MMA, Cin=512)
    for (int i = 0; i < 5; i++) {
        int Lin = L[1 + i], Lo = L[2 + i];
        conv_mma<<<dim3(8, (Lo + 127) / 128, B), 256, SMEMSZ>>>(
            xt_, (size_t)B * Lin * 512, ws_ + 2621440 + (size_t)i * 5242880, 2621440,
            br + i * 512, bufA, 512, 512, Lin, Lo);
        gn_stats_t<<<B * 32, 256>>>(bufA, mean_, istd_, Lo, 512, 32);
        int nb = (int)(((size_t)Lo * 512 / 4 + 255) / 256);
        if (i < 4) {
            size_t ps = (size_t)B * Lo * 512;
            ng_split<<<dim3(nb, B), 256>>>(bufA, mean_, istd_, gr + (i + 1) * 512,
                                           brr + (i + 1) * 512, xt_, ps, Lo, 512, 32);
        } else {
            ng_inplace<<<dim3(nb, B), 256>>>(bufA, mean_, istd_, gr + 5 * 512,
                                             brr + 5 * 512, Lo, 512, 32);
        }
    }

    int S = L[6];           // 976
    int NS = B * S;         // 7808

    // projection: feats[NS][1536]
    gemm_nt<<<dim3(1536 / 64, NS / 64), 128>>>(bufA, pw, pb, bufB, 512, 1536);

    // VQ
    float* sc = (float*)xt_;
    gemm_nt<<<dim3(1024 / 64, NS / 64), 128>>>(bufB, cbk, nullptr, sc, 1536, 1024);
    vq_argmin<<<(NS + 7) / 8, 256>>>(sc, cn_, idx_, NS);

    final_ln<<<NS, 256>>>(cbk, idx_, pos, mod, lng, lnb, out, S, NS);
}

// round 13
// speedup vs baseline: 2.4615x; 1.0701x over previous
#include <cuda_runtime.h>
#include <cuda_fp16.h>
#include <cuda_bf16.h>
#include <math.h>
#include <stdint.h>

__device__ float          g_bufA[128000000];
__device__ float          g_bufB[16000000];
__device__ __nv_bfloat16  g_xt[384000000];    // reused as __half planes
__device__ __nv_bfloat16  g_ws[43300000];     // reused as __half split weights
__device__ float          g_mean[512];
__device__ float          g_istd[512];
__device__ float          g_cnorm[1024];
__device__ int            g_idx[8192];

__device__ __forceinline__ float gelu_f(float x) {
    return 0.5f * x * (1.0f + erff(x * 0.7071067811865476f));
}
__device__ __forceinline__ uint32_t smem_u32(const void* p) {
    uint32_t a;
    asm("{ .reg .u64 t; cvta.to.shared.u64 t, %1; cvt.u32.u64 %0, t; }" : "=r"(a) : "l"(p));
    return a;
}
__device__ __forceinline__ void cpa16(uint32_t dst, const void* src) {
    asm volatile("cp.async.cg.shared.global [%0], [%1], 16;" :: "r"(dst), "l"(src));
}
__device__ __forceinline__ void cpa16z(uint32_t dst, const void* src, uint32_t sz) {
    asm volatile("cp.async.cg.shared.global [%0], [%1], 16, %2;" :: "r"(dst), "l"(src), "r"(sz));
}
__device__ __forceinline__ void ldmx4(uint32_t a, uint32_t* r) {
    asm volatile("ldmatrix.sync.aligned.m8n8.x4.shared.b16 {%0,%1,%2,%3}, [%4];"
                 : "=r"(r[0]), "=r"(r[1]), "=r"(r[2]), "=r"(r[3]) : "r"(a));
}
__device__ __forceinline__ void mma16816(float* c, const uint32_t* a, uint32_t b0, uint32_t b1) {
    asm volatile("mma.sync.aligned.m16n8k16.row.col.f32.f16.f16.f32 "
                 "{%0,%1,%2,%3}, {%4,%5,%6,%7}, {%8,%9}, {%0,%1,%2,%3};"
                 : "+f"(c[0]), "+f"(c[1]), "+f"(c[2]), "+f"(c[3])
                 : "r"(a[0]), "r"(a[1]), "r"(a[2]), "r"(a[3]), "r"(b0), "r"(b1));
}

struct f32x2 { unsigned long long u; };
__device__ __forceinline__ f32x2 pack2(float lo, float hi) {
    f32x2 r; asm("mov.b64 %0, {%1, %2};" : "=l"(r.u) : "f"(lo), "f"(hi)); return r;
}
__device__ __forceinline__ void fma2(f32x2 &d, f32x2 a, f32x2 b) {
    asm("fma.rn.f32x2 %0, %1, %2, %0;" : "+l"(d.u) : "l"(a.u), "l"(b.u));
}
__device__ __forceinline__ void unpack2(f32x2 v, float &lo, float &hi) {
    asm("mov.b64 {%0, %1}, %2;" : "=f"(lo), "=f"(hi) : "l"(v.u));
}

// conv0: Cin=1 -> yT[b][l][256]
__global__ __launch_bounds__(256)
void conv0_t(const float* __restrict__ x, const float* __restrict__ w,
             const float* __restrict__ bias, float* __restrict__ yT, int Lin, int Lout)
{
    __shared__ float Wsh[2560];
    __shared__ float Xsh[85];
    int b = blockIdx.y, l0 = blockIdx.x * 16, co = threadIdx.x;
    for (int i = co; i < 2560; i += 256) Wsh[i] = w[i];
    int g0 = 5 * l0 - 5;
    for (int i = co; i < 85; i += 256) {
        int gl = g0 + i;
        Xsh[i] = (gl >= 0 && gl < Lin) ? x[(size_t)b * Lin + gl] : 0.0f;
    }
    __syncthreads();
    float wr[10];
    #pragma unroll
    for (int t = 0; t < 10; t++) wr[t] = Wsh[co * 10 + t];
    float bv = bias[co];
    for (int j = 0; j < 16; j++) {
        int l = l0 + j;
        if (l >= Lout) break;
        float a = bv;
        #pragma unroll
        for (int t = 0; t < 10; t++) a = fmaf(wr[t], Xsh[5 * j + t], a);
        yT[((size_t)b * Lout + l) * 256 + co] = a;
    }
}

// All 6 layers' weights -> fp16 scaled 2-comp split, layout [comp][co][t][ci]
__global__ __launch_bounds__(256)
void wprep_all(const float* __restrict__ w1, const float* __restrict__ wr,
               __half* __restrict__ d)
{
    int L = blockIdx.y, co = blockIdx.x;
    int Cin = (L == 0) ? 256 : 512;
    const float* src = (L == 0) ? w1 : wr + (size_t)(L - 1) * 512 * 512 * 10;
    __half* dst = (L == 0) ? d : d + 2621440 + (size_t)(L - 1) * 5242880;
    size_t cs = (size_t)512 * 10 * Cin;
    for (int i = threadIdx.x; i < Cin * 10; i += 256) {
        int ci = i / 10, t = i - ci * 10;
        float v = src[((size_t)co * Cin + ci) * 10 + t];
        __half c0 = __float2half(v);
        __half c1 = __float2half((v - __half2float(c0)) * 2048.0f);
        size_t o = ((size_t)co * 10 + t) * Cin + ci;
        dst[o] = c0; dst[cs + o] = c1;
    }
}

// ---------------------------------------------------------------------------
// mma.sync fp16 conv. CTA 256thr/8 warps; tile M=128(l) x N=64(co); warp 32x32.
// K-chunk = 128 ci per tap (8 k16 steps); 2 scaled fp16 comps;
// products: x0w0 -> c[0], x0w1+x1w0 -> c[1]; fp64 drain g += c0 + c1/2048
// every 2 chunks (256 K-adds per fp32 group). 2-stage cp.async pipeline.
// Cin templated -> all chunk address math constant-folds.
// ---------------------------------------------------------------------------
#define ROWB   272            // 256B data + 16B pad (conflict-free ldmatrix)
#define ACMP   34816          // 128 rows * 272B
#define BCMP   17408          // 64 rows * 272B
#define AHALF  69632          // 2 A comps
#define BUFB   104448         // A(2) + B(2)
#define NSTG   2

template<int CIN>
__global__ __launch_bounds__(256)
void conv_mma(const __half* __restrict__ xs, size_t planeStride,
              const __half* __restrict__ ws, size_t wcs,
              const float* __restrict__ bias, float* __restrict__ yT,
              int Cout, int Lin, int Lout)
{
    extern __shared__ __align__(128) char smem[];
    uint32_t sbase = smem_u32(smem);
    int tid = threadIdx.x, wid = tid >> 5, lane = tid & 31;
    int wm = wid & 3, wn = wid >> 2;          // 4 x 2 warp grid
    int co0 = blockIdx.x * 64;
    int l0  = blockIdx.y * 128;
    int b   = blockIdx.z;

    const __half* xb = xs + (size_t)b * (size_t)Lin * CIN;
    constexpr int NKB = (CIN == 256) ? 1 : 2;   // log2(chunks per tap)
    constexpr int NKC = 1 << NKB;               // ci chunks of 128
    constexpr int NC  = 10 * NKC;

    float  c[2][2][4][4];     // [accSet][mt][nt][q]
    double g[2][4][4];
    #pragma unroll
    for (int s = 0; s < 2; s++)
        #pragma unroll
        for (int i = 0; i < 2; i++)
            #pragma unroll
            for (int j = 0; j < 4; j++)
                #pragma unroll
                for (int q = 0; q < 4; q++) c[s][i][j][q] = 0.0f;
    #pragma unroll
    for (int i = 0; i < 2; i++)
        #pragma unroll
        for (int j = 0; j < 4; j++)
            #pragma unroll
            for (int q = 0; q < 4; q++) g[i][j][q] = 0.0;

    #define ISSUE(kk) do {                                                            \
        int _k = (kk);                                                                \
        int _s = _k & 1, _t = _k >> NKB, _ci0 = (_k & (NKC - 1)) << 7;                \
        uint32_t Ab = sbase + _s * BUFB;                                              \
        uint32_t Bb = Ab + AHALF;                                                     \
        int _r0 = 2 * l0 - 5 + _t;                                                    \
        _Pragma("unroll")                                                             \
        for (int j = 0; j < 16; j++) {         /* A: 4096 segs */                     \
            int idx = tid + j * 256;                                                  \
            int comp = idx >> 11, rem = idx & 2047;                                   \
            int row = rem >> 4, seg = rem & 15;                                       \
            int r = _r0 + 2 * row;                                                    \
            int ok = (r >= 0 && r < Lin);                                             \
            const __half* sa = xb + (size_t)comp * planeStride                        \
                + (size_t)(ok ? r : 0) * CIN + _ci0 + (seg << 3);                     \
            cpa16z(Ab + comp * ACMP + row * ROWB + (seg << 4), sa, ok ? 16u : 0u);    \
        }                                                                             \
        _Pragma("unroll")                                                             \
        for (int j = 0; j < 8; j++) {          /* B: 2048 segs */                     \
            int idx = tid + j * 256;                                                  \
            int comp = idx >> 10, rem = idx & 1023;                                   \
            int row = rem >> 4, seg = rem & 15;                                       \
            const __half* sbp = ws + (size_t)comp * wcs                               \
                + ((size_t)(co0 + row) * 10 + _t) * CIN + _ci0 + (seg << 3);          \
            cpa16(Bb + comp * BCMP + row * ROWB + (seg << 4), sbp);                   \
        }                                                                             \
        asm volatile("cp.async.commit_group;" ::: "memory");                          \
    } while (0)

    ISSUE(0);
    for (int k = 0; k < NC; k++) {
        if (k + 1 < NC) {
            ISSUE(k + 1);
            asm volatile("cp.async.wait_group 1;" ::: "memory");
        } else {
            asm volatile("cp.async.wait_group 0;" ::: "memory");
        }
        __syncthreads();
        uint32_t Ab = sbase + (k & 1) * BUFB;
        uint32_t Bb = Ab + AHALF;
        uint32_t aw = Ab + (wm * 32 + (lane & 15)) * ROWB + (lane >> 4) * 16;
        uint32_t bw = Bb + (wn * 32 + ((lane >> 4) << 3) + (lane & 7)) * ROWB
                        + ((lane >> 3) & 1) * 16;
        #pragma unroll
        for (int ks = 0; ks < 8; ks++) {
            uint32_t a[2][2][4], bf[2][2][4];   // [comp][mt|n2][4]
            #pragma unroll
            for (int cp = 0; cp < 2; cp++)
                #pragma unroll
                for (int mt = 0; mt < 2; mt++)
                    ldmx4(aw + cp * ACMP + mt * (16 * ROWB) + ks * 32, a[cp][mt]);
            #pragma unroll
            for (int cp = 0; cp < 2; cp++)
                #pragma unroll
                for (int n2 = 0; n2 < 2; n2++)
                    ldmx4(bw + cp * BCMP + n2 * (16 * ROWB) + ks * 32, bf[cp][n2]);
            // product 0: x0*w0 -> c[0];  products 1,2: x0*w1, x1*w0 -> c[1]
            #pragma unroll
            for (int mt = 0; mt < 2; mt++)
                #pragma unroll
                for (int nt = 0; nt < 4; nt++) {
                    uint32_t b0a = bf[0][nt >> 1][(nt & 1) * 2];
                    uint32_t b0b = bf[0][nt >> 1][(nt & 1) * 2 + 1];
                    uint32_t b1a = bf[1][nt >> 1][(nt & 1) * 2];
                    uint32_t b1b = bf[1][nt >> 1][(nt & 1) * 2 + 1];
                    mma16816(c[0][mt][nt], a[0][mt], b0a, b0b);
                    mma16816(c[1][mt][nt], a[0][mt], b1a, b1b);
                    mma16816(c[1][mt][nt], a[1][mt], b0a, b0b);
                }
        }
        if ((k & 1) == 1 || k == NC - 1) {
            #pragma unroll
            for (int mt = 0; mt < 2; mt++)
                #pragma unroll
                for (int nt = 0; nt < 4; nt++)
                    #pragma unroll
                    for (int q = 0; q < 4; q++) {
                        g[mt][nt][q] += (double)c[0][mt][nt][q]
                                      + (double)c[1][mt][nt][q] * (1.0 / 2048.0);
                        c[0][mt][nt][q] = 0.0f;
                        c[1][mt][nt][q] = 0.0f;
                    }
        }
        __syncthreads();
    }

    #pragma unroll
    for (int mt = 0; mt < 2; mt++) {
        int lr = l0 + wm * 32 + mt * 16 + (lane >> 2);
        #pragma unroll
        for (int nt = 0; nt < 4; nt++) {
            int col = co0 + wn * 32 + nt * 8 + (lane & 3) * 2;
            float b0 = bias[col], b1 = bias[col + 1];
            if (lr < Lout) {
                float2 v = make_float2((float)g[mt][nt][0] + b0, (float)g[mt][nt][1] + b1);
                *(float2*)&yT[((size_t)b * Lout + lr) * Cout + col] = v;
            }
            if (lr + 8 < Lout) {
                float2 v = make_float2((float)g[mt][nt][2] + b0, (float)g[mt][nt][3] + b1);
                *(float2*)&yT[((size_t)b * Lout + lr + 8) * Cout + col] = v;
            }
        }
    }
}

// GN stats over [b][l][C]
__global__ __launch_bounds__(256)
void gn_stats_t(const float* __restrict__ x, float* __restrict__ mean,
                float* __restrict__ istd, int L, int C, int G)
{
    int blk = blockIdx.x, b = blk / G, g = blk % G;
    const float* p = x + (size_t)b * L * C + g * 16;
    float s = 0.0f, s2 = 0.0f;
    int tot = L * 16;
    for (int i = threadIdx.x; i < tot; i += 256) {
        int l = i >> 4, cc = i & 15;
        float v = p[(size_t)l * C + cc];
        s += v; s2 = fmaf(v, v, s2);
    }
    __shared__ float sa[256], sbm[256];
    int tid = threadIdx.x;
    sa[tid] = s; sbm[tid] = s2;
    __syncthreads();
    for (int o = 128; o > 0; o >>= 1) {
        if (tid < o) { sa[tid] += sa[tid + o]; sbm[tid] += sbm[tid + o]; }
        __syncthreads();
    }
    if (tid == 0) {
        float m = sa[0] / (float)tot;
        float var = sbm[0] / (float)tot - m * m;
        mean[blk] = m;
        istd[blk] = rsqrtf(var + 1e-5f);
    }
}

// GN apply + GELU + scaled fp16 2-way split -> planes
__global__ __launch_bounds__(256)
void ng_split(const float* __restrict__ x, const float* __restrict__ mean,
              const float* __restrict__ istd, const float* __restrict__ gma,
              const float* __restrict__ bta, __half* __restrict__ xs,
              size_t ps, int L, int C, int G)
{
    int b = blockIdx.y;
    size_t i4 = (size_t)blockIdx.x * 256 + threadIdx.x;
    size_t n4 = (size_t)L * C >> 2;
    if (i4 >= n4) return;
    size_t base = (size_t)b * L * C;
    float4 v = ((const float4*)(x + base))[i4];
    int cc = (int)((i4 << 2) % (size_t)C);
    int bg = b * G + (cc >> 4);
    float mu = mean[bg], is = istd[bg];
    float o[4] = {v.x, v.y, v.z, v.w};
    __half p0[4], p1[4];
    #pragma unroll
    for (int j = 0; j < 4; j++) {
        float h = gelu_f((o[j] - mu) * is * gma[cc + j] + bta[cc + j]);
        __half a = __float2half(h);
        p0[j] = a;
        p1[j] = __float2half((h - __half2float(a)) * 2048.0f);
    }
    ((uint64_t*)(xs + base))[i4]      = *(uint64_t*)p0;
    ((uint64_t*)(xs + ps + base))[i4] = *(uint64_t*)p1;
}

__global__ __launch_bounds__(256)
void ng_inplace(float* __restrict__ x, const float* __restrict__ mean,
                const float* __restrict__ istd, const float* __restrict__ gma,
                const float* __restrict__ bta, int L, int C, int G)
{
    int b = blockIdx.y;
    size_t i4 = (size_t)blockIdx.x * 256 + threadIdx.x;
    size_t n4 = (size_t)L * C >> 2;
    if (i4 >= n4) return;
    size_t base = (size_t)b * L * C;
    float4 v = ((const float4*)(x + base))[i4];
    int cc = (int)((i4 << 2) % (size_t)C);
    int bg = b * G + (cc >> 4);
    float mu = mean[bg], is = istd[bg];
    v.x = gelu_f((v.x - mu) * is * gma[cc + 0] + bta[cc + 0]);
    v.y = gelu_f((v.y - mu) * is * gma[cc + 1] + bta[cc + 1]);
    v.z = gelu_f((v.z - mu) * is * gma[cc + 2] + bta[cc + 2]);
    v.w = gelu_f((v.w - mu) * is * gma[cc + 3] + bta[cc + 3]);
    ((float4*)(x + base))[i4] = v;
}

// SIMT f32x2 GEMM tail
__global__ __launch_bounds__(128)
void gemm_nt(const float* __restrict__ A, const float* __restrict__ B,
             const float* __restrict__ bias, float* __restrict__ out, int K, int Nj)
{
    __shared__ float As[64][17], Bs[64][17];
    int tid = threadIdx.x;
    int i0 = blockIdx.y * 64, j0 = blockIdx.x * 64;
    int isub = tid >> 4, jsub = tid & 15;
    f32x2 acc[8][2];
    #pragma unroll
    for (int i = 0; i < 8; i++) { acc[i][0].u = 0ull; acc[i][1].u = 0ull; }
    for (int k0 = 0; k0 < K; k0 += 16) {
        __syncthreads();
        for (int x = tid; x < 1024; x += 128) {
            int r = x >> 4, cc = x & 15;
            As[r][cc] = A[(size_t)(i0 + r) * K + k0 + cc];
            Bs[r][cc] = B[(size_t)(j0 + r) * K + k0 + cc];
        }
        __syncthreads();
        #pragma unroll 4
        for (int k = 0; k < 16; k++) {
            f32x2 b0 = pack2(Bs[jsub * 4 + 0][k], Bs[jsub * 4 + 1][k]);
            f32x2 b1 = pack2(Bs[jsub * 4 + 2][k], Bs[jsub * 4 + 3][k]);
            #pragma unroll
            for (int ii = 0; ii < 8; ii++) {
                float a = As[isub + (ii << 3)][k];
                f32x2 a2 = pack2(a, a);
                fma2(acc[ii][0], a2, b0);
                fma2(acc[ii][1], a2, b1);
            }
        }
    }
    int j = j0 + jsub * 4;
    float bv0 = bias ? bias[j] : 0.0f, bv1 = bias ? bias[j + 1] : 0.0f;
    float bv2 = bias ? bias[j + 2] : 0.0f, bv3 = bias ? bias[j + 3] : 0.0f;
    #pragma unroll
    for (int ii = 0; ii < 8; ii++) {
        int i = i0 + isub + (ii << 3);
        float o0, o1, o2, o3;
        unpack2(acc[ii][0], o0, o1);
        unpack2(acc[ii][1], o2, o3);
        float* p = out + (size_t)i * Nj + j;
        p[0] = o0 + bv0; p[1] = o1 + bv1; p[2] = o2 + bv2; p[3] = o3 + bv3;
    }
}

__global__ __launch_bounds__(256)
void cb_norms(const float* __restrict__ cbk, float* __restrict__ cn)
{
    const float4* row = (const float4*)(cbk + (size_t)blockIdx.x * 1536);
    float s = 0.0f;
    for (int i = threadIdx.x; i < 384; i += 256) {
        float4 v = row[i];
        s += v.x * v.x + v.y * v.y + v.z * v.z + v.w * v.w;
    }
    __shared__ float sa[256];
    int tid = threadIdx.x;
    sa[tid] = s;
    __syncthreads();
    for (int o = 128; o > 0; o >>= 1) {
        if (tid < o) sa[tid] += sa[tid + o];
        __syncthreads();
    }
    if (tid == 0) cn[blockIdx.x] = sa[0];
}

__global__ __launch_bounds__(256)
void vq_argmin(const float* __restrict__ sc, const float* __restrict__ cn,
               int* __restrict__ idx, int NS)
{
    int g = blockIdx.x * 8 + (threadIdx.x >> 5);
    int lane = threadIdx.x & 31;
    if (g >= NS) return;
    const float* s = sc + (size_t)g * 1024;
    float best = 3.4e38f; int bi = 1 << 30;
    for (int j = lane; j < 1024; j += 32) {
        float d = fmaf(-2.0f, s[j], cn[j]);
        if (d < best) { best = d; bi = j; }
    }
    #pragma unroll
    for (int o = 16; o > 0; o >>= 1) {
        float ov = __shfl_xor_sync(0xffffffffu, best, o);
        int   oi = __shfl_xor_sync(0xffffffffu, bi,   o);
        if (ov < best || (ov == best && oi < bi)) { best = ov; bi = oi; }
    }
    if (lane == 0) idx[g] = bi;
}

__global__ __launch_bounds__(256)
void final_ln(const float* __restrict__ cbk, const int* __restrict__ idx,
              const float* __restrict__ pos, const float* __restrict__ mod,
              const float* __restrict__ lng, const float* __restrict__ lnb,
              float* __restrict__ out, int S, int NS)
{
    int n = blockIdx.x, s = n % S, tid = threadIdx.x;
    __shared__ float row[1536];
    __shared__ float sa[256], sbm[256];
    const float* c = cbk + (size_t)idx[n] * 1536;
    const float* p = pos + (size_t)s * 1536;
    float ls = 0.0f, ls2 = 0.0f;
    for (int e = tid; e < 1536; e += 256) {
        float v = c[e] + p[e] + mod[e];
        row[e] = v;
        ls += v; ls2 = fmaf(v, v, ls2);
    }
    sa[tid] = ls; sbm[tid] = ls2;
    __syncthreads();
    for (int o = 128; o > 0; o >>= 1) {
        if (tid < o) { sa[tid] += sa[tid + o]; sbm[tid] += sbm[tid + o]; }
        __syncthreads();
    }
    float m = sa[0] * (1.0f / 1536.0f);
    float var = sbm[0] * (1.0f / 1536.0f) - m * m;
    float r = rsqrtf(var + 1e-5f);
    for (int e = tid; e < 1536; e += 256)
        out[(size_t)n * 1536 + e] = (row[e] - m) * r * lng[e] + lnb[e];
    if (tid == 0) {
        out[(size_t)NS * 1536 + n]      = 1.0f;
        out[(size_t)NS * 1536 + NS + n] = (float)idx[n];
    }
}

extern "C" void kernel_launch(void* const* d_in, const int* in_sizes, int n_in,
                              void* d_out, int out_size)
{
    const float* wav = (const float*)d_in[0];
    const float* w0  = (const float*)d_in[1];
    const float* b0  = (const float*)d_in[2];
    const float* w1  = (const float*)d_in[3];
    const float* b1  = (const float*)d_in[4];
    const float* wr  = (const float*)d_in[5];
    const float* br  = (const float*)d_in[6];
    const float* g0  = (const float*)d_in[7];
    const float* bb0 = (const float*)d_in[8];
    const float* gr  = (const float*)d_in[9];
    const float* brr = (const float*)d_in[10];
    const float* pw  = (const float*)d_in[11];
    const float* pb  = (const float*)d_in[12];
    const float* cbk = (const float*)d_in[13];
    const float* pos = (const float*)d_in[14];
    const float* mod = (const float*)d_in[15];
    const float* lng = (const float*)d_in[16];
    const float* lnb = (const float*)d_in[17];
    float* out = (float*)d_out;

    const int B = 8;
    int Lw = in_sizes[0] / B;
    int L[7];
    L[0] = Lw / 5 + 1;
    for (int i = 1; i <= 6; i++) L[i] = L[i - 1] / 2 + 1;

    float *bufA, *bufB, *mean_, *istd_, *cn_;
    __half *xt_, *ws_;
    int *idx_;
    cudaGetSymbolAddress((void**)&bufA,  g_bufA);
    cudaGetSymbolAddress((void**)&bufB,  g_bufB);
    cudaGetSymbolAddress((void**)&xt_,   g_xt);
    cudaGetSymbolAddress((void**)&ws_,   g_ws);
    cudaGetSymbolAddress((void**)&mean_, g_mean);
    cudaGetSymbolAddress((void**)&istd_, g_istd);
    cudaGetSymbolAddress((void**)&cn_,   g_cnorm);
    cudaGetSymbolAddress((void**)&idx_,  g_idx);

    const int SMEMSZ = NSTG * BUFB;   // 208896
    cudaFuncSetAttribute(conv_mma<256>, cudaFuncAttributeMaxDynamicSharedMemorySize, SMEMSZ);
    cudaFuncSetAttribute(conv_mma<512>, cudaFuncAttributeMaxDynamicSharedMemorySize, SMEMSZ);

    cb_norms<<<1024, 256>>>(cbk, cn_);
    wprep_all<<<dim3(512, 6), 256>>>(w1, wr, ws_);

    conv0_t<<<dim3((L[0] + 15) / 16, B), 256>>>(wav, w0, b0, bufA, Lw, L[0]);
    gn_stats_t<<<B * 16, 256>>>(bufA, mean_, istd_, L[0], 256, 16);
    {
        size_t ps = (size_t)B * L[0] * 256;
        int nb = (int)(((size_t)L[0] * 256 / 4 + 255) / 256);
        ng_split<<<dim3(nb, B), 256>>>(bufA, mean_, istd_, g0, bb0, xt_, ps, L[0], 256, 16);
    }

    // layer 1 (MMA, Cin=256)
    conv_mma<256><<<dim3(8, (L[1] + 127) / 128, B), 256, SMEMSZ>>>(
        xt_, (size_t)B * L[0] * 256, ws_, 1310720, b1, bufA, 512, L[0], L[1]);
    gn_stats_t<<<B * 32, 256>>>(bufA, mean_, istd_, L[1], 512, 32);
    {
        size_t ps = (size_t)B * L[1] * 512;
        int nb = (int)(((size_t)L[1] * 512 / 4 + 255) / 256);
        ng_split<<<dim3(nb, B), 256>>>(bufA, mean_, istd_, gr, brr, xt_, ps, L[1], 512, 32);
    }

    // layers 2..6 (MMA, Cin=512)
    for (int i = 0; i < 5; i++) {
        int Lin = L[1 + i], Lo = L[2 + i];
        conv_mma<512><<<dim3(8, (Lo + 127) / 128, B), 256, SMEMSZ>>>(
            xt_, (size_t)B * Lin * 512, ws_ + 2621440 + (size_t)i * 5242880, 2621440,
            br + i * 512, bufA, 512, Lin, Lo);
        gn_stats_t<<<B * 32, 256>>>(bufA, mean_, istd_, Lo, 512, 32);
        int nb = (int)(((size_t)Lo * 512 / 4 + 255) / 256);
        if (i < 4) {
            size_t ps = (size_t)B * Lo * 512;
            ng_split<<<dim3(nb, B), 256>>>(bufA, mean_, istd_, gr + (i + 1) * 512,
                                           brr + (i + 1) * 512, xt_, ps, Lo, 512, 32);
        } else {
            ng_inplace<<<dim3(nb, B), 256>>>(bufA, mean_, istd_, gr + 5 * 512,
                                             brr + 5 * 512, Lo, 512, 32);
        }
    }

    int S = L[6];           // 976
    int NS = B * S;         // 7808

    // projection: feats[NS][1536]
    gemm_nt<<<dim3(1536 / 64, NS / 64), 128>>>(bufA, pw, pb, bufB, 512, 1536);

    // VQ
    float* sc = (float*)xt_;
    gemm_nt<<<dim3(1024 / 64, NS / 64), 128>>>(bufB, cbk, nullptr, sc, 1536, 1024);
    vq_argmin<<<(NS + 7) / 8, 256>>>(sc, cn_, idx_, NS);

    final_ln<<<NS, 256>>>(cbk, idx_, pos, mod, lng, lnb, out, S, NS);
}

// round 14
// speedup vs baseline: 2.5686x; 1.0435x over previous
#include <cuda_runtime.h>
#include <cuda_fp16.h>
#include <cuda_bf16.h>
#include <math.h>
#include <stdint.h>

__device__ float          g_bufA[128000000];
__device__ float          g_bufB[16000000];
__device__ __nv_bfloat16  g_xt[384000000];    // reused as __half planes
__device__ __nv_bfloat16  g_ws[43300000];     // reused as __half split weights
__device__ float          g_mean[512];
__device__ float          g_istd[512];
__device__ float          g_cnorm[1024];
__device__ int            g_idx[8192];

__device__ __forceinline__ float gelu_f(float x) {
    return 0.5f * x * (1.0f + erff(x * 0.7071067811865476f));
}
__device__ __forceinline__ uint32_t smem_u32(const void* p) {
    uint32_t a;
    asm("{ .reg .u64 t; cvta.to.shared.u64 t, %1; cvt.u32.u64 %0, t; }" : "=r"(a) : "l"(p));
    return a;
}
__device__ __forceinline__ void cpa16(uint32_t dst, const void* src) {
    asm volatile("cp.async.cg.shared.global [%0], [%1], 16;" :: "r"(dst), "l"(src));
}
__device__ __forceinline__ void cpa16z(uint32_t dst, const void* src, uint32_t sz) {
    asm volatile("cp.async.cg.shared.global [%0], [%1], 16, %2;" :: "r"(dst), "l"(src), "r"(sz));
}
__device__ __forceinline__ void ldmx4(uint32_t a, uint32_t* r) {
    asm volatile("ldmatrix.sync.aligned.m8n8.x4.shared.b16 {%0,%1,%2,%3}, [%4];"
                 : "=r"(r[0]), "=r"(r[1]), "=r"(r[2]), "=r"(r[3]) : "r"(a));
}
__device__ __forceinline__ void mma16816(float* c, const uint32_t* a, uint32_t b0, uint32_t b1) {
    asm volatile("mma.sync.aligned.m16n8k16.row.col.f32.f16.f16.f32 "
                 "{%0,%1,%2,%3}, {%4,%5,%6,%7}, {%8,%9}, {%0,%1,%2,%3};"
                 : "+f"(c[0]), "+f"(c[1]), "+f"(c[2]), "+f"(c[3])
                 : "r"(a[0]), "r"(a[1]), "r"(a[2]), "r"(a[3]), "r"(b0), "r"(b1));
}

struct f32x2 { unsigned long long u; };
__device__ __forceinline__ f32x2 pack2(float lo, float hi) {
    f32x2 r; asm("mov.b64 %0, {%1, %2};" : "=l"(r.u) : "f"(lo), "f"(hi)); return r;
}
__device__ __forceinline__ void fma2(f32x2 &d, f32x2 a, f32x2 b) {
    asm("fma.rn.f32x2 %0, %1, %2, %0;" : "+l"(d.u) : "l"(a.u), "l"(b.u));
}
__device__ __forceinline__ void unpack2(f32x2 v, float &lo, float &hi) {
    asm("mov.b64 {%0, %1}, %2;" : "=f"(lo), "=f"(hi) : "l"(v.u));
}

// conv0: Cin=1 -> yT[b][l][256]
__global__ __launch_bounds__(256)
void conv0_t(const float* __restrict__ x, const float* __restrict__ w,
             const float* __restrict__ bias, float* __restrict__ yT, int Lin, int Lout)
{
    __shared__ float Wsh[2560];
    __shared__ float Xsh[85];
    int b = blockIdx.y, l0 = blockIdx.x * 16, co = threadIdx.x;
    for (int i = co; i < 2560; i += 256) Wsh[i] = w[i];
    int g0 = 5 * l0 - 5;
    for (int i = co; i < 85; i += 256) {
        int gl = g0 + i;
        Xsh[i] = (gl >= 0 && gl < Lin) ? x[(size_t)b * Lin + gl] : 0.0f;
    }
    __syncthreads();
    float wr[10];
    #pragma unroll
    for (int t = 0; t < 10; t++) wr[t] = Wsh[co * 10 + t];
    float bv = bias[co];
    for (int j = 0; j < 16; j++) {
        int l = l0 + j;
        if (l >= Lout) break;
        float a = bv;
        #pragma unroll
        for (int t = 0; t < 10; t++) a = fmaf(wr[t], Xsh[5 * j + t], a);
        yT[((size_t)b * Lout + l) * 256 + co] = a;
    }
}

// All 6 layers' weights -> fp16 scaled 2-comp split, layout [comp][co][t][ci]
__global__ __launch_bounds__(256)
void wprep_all(const float* __restrict__ w1, const float* __restrict__ wr,
               __half* __restrict__ d)
{
    int L = blockIdx.y, co = blockIdx.x;
    int Cin = (L == 0) ? 256 : 512;
    const float* src = (L == 0) ? w1 : wr + (size_t)(L - 1) * 512 * 512 * 10;
    __half* dst = (L == 0) ? d : d + 2621440 + (size_t)(L - 1) * 5242880;
    size_t cs = (size_t)512 * 10 * Cin;
    for (int i = threadIdx.x; i < Cin * 10; i += 256) {
        int ci = i / 10, t = i - ci * 10;
        float v = src[((size_t)co * Cin + ci) * 10 + t];
        __half c0 = __float2half(v);
        __half c1 = __float2half((v - __half2float(c0)) * 2048.0f);
        size_t o = ((size_t)co * 10 + t) * Cin + ci;
        dst[o] = c0; dst[cs + o] = c1;
    }
}

// ---------------------------------------------------------------------------
// mma.sync fp16 conv. CTA 256thr/8 warps; tile M=128(l) x N=64(co); warp 32x32.
// K-chunk = 128 ci per tap (8 k16 steps); 2 scaled fp16 comps;
// products: x0w0 -> c[0], x0w1+x1w0 -> c[1]; fp64 drain every 2 chunks.
// 2-stage cp.async pipeline. Interior CTAs use incremental-pointer loads
// (A and B global addresses advance exactly +128 halves per chunk).
// ---------------------------------------------------------------------------
#define ROWB   272            // 256B data + 16B pad (conflict-free ldmatrix)
#define ACMP   34816          // 128 rows * 272B
#define BCMP   17408          // 64 rows * 272B
#define AHALF  69632          // 2 A comps
#define BUFB   104448         // A(2) + B(2)
#define NSTG   2

template<int CIN>
__global__ __launch_bounds__(256)
void conv_mma(const __half* __restrict__ xs, size_t planeStride,
              const __half* __restrict__ ws, size_t wcs,
              const float* __restrict__ bias, float* __restrict__ yT,
              int Cout, int Lin, int Lout)
{
    extern __shared__ __align__(128) char smem[];
    uint32_t sbase = smem_u32(smem);
    int tid = threadIdx.x, wid = tid >> 5, lane = tid & 31;
    int wm = wid & 3, wn = wid >> 2;          // 4 x 2 warp grid
    int co0 = blockIdx.x * 64;
    int l0  = blockIdx.y * 128;
    int b   = blockIdx.z;

    const __half* xb = xs + (size_t)b * (size_t)Lin * CIN;
    constexpr int NKB = (CIN == 256) ? 1 : 2;   // log2(chunks per tap)
    constexpr int NKC = 1 << NKB;               // ci chunks of 128
    constexpr int NC  = 10 * NKC;

    float  c[2][2][4][4];     // [accSet][mt][nt][q]
    double g[2][4][4];
    #pragma unroll
    for (int s = 0; s < 2; s++)
        #pragma unroll
        for (int i = 0; i < 2; i++)
            #pragma unroll
            for (int j = 0; j < 4; j++)
                #pragma unroll
                for (int q = 0; q < 4; q++) c[s][i][j][q] = 0.0f;
    #pragma unroll
    for (int i = 0; i < 2; i++)
        #pragma unroll
        for (int j = 0; j < 4; j++)
            #pragma unroll
            for (int q = 0; q < 4; q++) g[i][j][q] = 0.0;

    // ---- compute body for chunk kk (shared by both load paths) ----
    #define COMPUTE(kk) do {                                                          \
        int _kc = (kk);                                                               \
        uint32_t Ab = sbase + (_kc & 1) * BUFB;                                       \
        uint32_t Bb = Ab + AHALF;                                                     \
        uint32_t aw = Ab + (wm * 32 + (lane & 15)) * ROWB + (lane >> 4) * 16;         \
        uint32_t bw = Bb + (wn * 32 + ((lane >> 4) << 3) + (lane & 7)) * ROWB         \
                        + ((lane >> 3) & 1) * 16;                                     \
        _Pragma("unroll")                                                             \
        for (int ks = 0; ks < 8; ks++) {                                              \
            uint32_t a[2][2][4], bf[2][2][4];                                         \
            _Pragma("unroll")                                                         \
            for (int cp = 0; cp < 2; cp++)                                            \
                _Pragma("unroll")                                                     \
                for (int mt = 0; mt < 2; mt++)                                        \
                    ldmx4(aw + cp * ACMP + mt * (16 * ROWB) + ks * 32, a[cp][mt]);    \
            _Pragma("unroll")                                                         \
            for (int cp = 0; cp < 2; cp++)                                            \
                _Pragma("unroll")                                                     \
                for (int n2 = 0; n2 < 2; n2++)                                        \
                    ldmx4(bw + cp * BCMP + n2 * (16 * ROWB) + ks * 32, bf[cp][n2]);   \
            _Pragma("unroll")                                                         \
            for (int mt = 0; mt < 2; mt++)                                            \
                _Pragma("unroll")                                                     \
                for (int nt = 0; nt < 4; nt++) {                                      \
                    uint32_t b0a = bf[0][nt >> 1][(nt & 1) * 2];                      \
                    uint32_t b0b = bf[0][nt >> 1][(nt & 1) * 2 + 1];                  \
                    uint32_t b1a = bf[1][nt >> 1][(nt & 1) * 2];                      \
                    uint32_t b1b = bf[1][nt >> 1][(nt & 1) * 2 + 1];                  \
                    mma16816(c[0][mt][nt], a[0][mt], b0a, b0b);                       \
                    mma16816(c[1][mt][nt], a[0][mt], b1a, b1b);                       \
                    mma16816(c[1][mt][nt], a[1][mt], b0a, b0b);                       \
                }                                                                     \
        }                                                                             \
        if ((_kc & 1) == 1 || _kc == NC - 1) {                                        \
            _Pragma("unroll")                                                         \
            for (int mt = 0; mt < 2; mt++)                                            \
                _Pragma("unroll")                                                     \
                for (int nt = 0; nt < 4; nt++)                                        \
                    _Pragma("unroll")                                                 \
                    for (int q = 0; q < 4; q++) {                                     \
                        g[mt][nt][q] += (double)c[0][mt][nt][q]                       \
                                      + (double)c[1][mt][nt][q] * (1.0 / 2048.0);     \
                        c[0][mt][nt][q] = 0.0f;                                       \
                        c[1][mt][nt][q] = 0.0f;                                       \
                    }                                                                 \
        }                                                                             \
        __syncthreads();                                                              \
    } while (0)

    bool interior = (l0 >= 3) && (2 * l0 + 258 < Lin);

    if (interior) {
        // incremental-pointer fast path: both A and B advance +128 halves/chunk
        int row0 = tid >> 4, seg = tid & 15;
        const __half* pA = xb + (size_t)(2 * l0 - 5 + 2 * row0) * CIN + (seg << 3);
        const __half* pB = ws + ((size_t)(co0 + row0) * 10) * CIN + (seg << 3);
        uint32_t smA = (uint32_t)(row0 * ROWB + (seg << 4));
        int fsi = 0;
        #define ISSUE_F() do {                                                        \
            uint32_t Ab = sbase + (uint32_t)(fsi & 1) * BUFB + smA;                   \
            uint32_t Bb = sbase + (uint32_t)(fsi & 1) * BUFB + AHALF + smA;           \
            _Pragma("unroll")                                                         \
            for (int cp = 0; cp < 2; cp++)                                            \
                _Pragma("unroll")                                                     \
                for (int jj = 0; jj < 8; jj++)                                        \
                    cpa16(Ab + cp * ACMP + jj * (16 * ROWB),                          \
                          pA + (size_t)cp * planeStride + jj * (32 * CIN));           \
            _Pragma("unroll")                                                         \
            for (int cp = 0; cp < 2; cp++)                                            \
                _Pragma("unroll")                                                     \
                for (int jj = 0; jj < 4; jj++)                                        \
                    cpa16(Bb + cp * BCMP + jj * (16 * ROWB),                          \
                          pB + (size_t)cp * wcs + jj * (160 * CIN));                  \
            asm volatile("cp.async.commit_group;" ::: "memory");                      \
            pA += 128; pB += 128; fsi++;                                              \
        } while (0)
        ISSUE_F();
        for (int k = 0; k < NC; k++) {
            if (k + 1 < NC) {
                ISSUE_F();
                asm volatile("cp.async.wait_group 1;" ::: "memory");
            } else {
                asm volatile("cp.async.wait_group 0;" ::: "memory");
            }
            __syncthreads();
            COMPUTE(k);
        }
    } else {
        #define ISSUE_S(kk) do {                                                      \
            int _k = (kk);                                                            \
            int _s = _k & 1, _t = _k >> NKB, _ci0 = (_k & (NKC - 1)) << 7;            \
            uint32_t Ab = sbase + _s * BUFB;                                          \
            uint32_t Bb = Ab + AHALF;                                                 \
            int _r0 = 2 * l0 - 5 + _t;                                                \
            _Pragma("unroll")                                                         \
            for (int j = 0; j < 16; j++) {                                            \
                int idx = tid + j * 256;                                              \
                int comp = idx >> 11, rem = idx & 2047;                               \
                int row = rem >> 4, sg = rem & 15;                                    \
                int r = _r0 + 2 * row;                                                \
                int ok = (r >= 0 && r < Lin);                                         \
                const __half* sa = xb + (size_t)comp * planeStride                    \
                    + (size_t)(ok ? r : 0) * CIN + _ci0 + (sg << 3);                  \
                cpa16z(Ab + comp * ACMP + row * ROWB + (sg << 4), sa, ok ? 16u : 0u); \
            }                                                                         \
            _Pragma("unroll")                                                         \
            for (int j = 0; j < 8; j++) {                                             \
                int idx = tid + j * 256;                                              \
                int comp = idx >> 10, rem = idx & 1023;                               \
                int row = rem >> 4, sg = rem & 15;                                    \
                const __half* sbp = ws + (size_t)comp * wcs                           \
                    + ((size_t)(co0 + row) * 10 + _t) * CIN + _ci0 + (sg << 3);       \
                cpa16(Bb + comp * BCMP + row * ROWB + (sg << 4), sbp);                \
            }                                                                         \
            asm volatile("cp.async.commit_group;" ::: "memory");                      \
        } while (0)
        ISSUE_S(0);
        for (int k = 0; k < NC; k++) {
            if (k + 1 < NC) {
                ISSUE_S(k + 1);
                asm volatile("cp.async.wait_group 1;" ::: "memory");
            } else {
                asm volatile("cp.async.wait_group 0;" ::: "memory");
            }
            __syncthreads();
            COMPUTE(k);
        }
    }

    #pragma unroll
    for (int mt = 0; mt < 2; mt++) {
        int lr = l0 + wm * 32 + mt * 16 + (lane >> 2);
        #pragma unroll
        for (int nt = 0; nt < 4; nt++) {
            int col = co0 + wn * 32 + nt * 8 + (lane & 3) * 2;
            float b0 = bias[col], b1 = bias[col + 1];
            if (lr < Lout) {
                float2 v = make_float2((float)g[mt][nt][0] + b0, (float)g[mt][nt][1] + b1);
                *(float2*)&yT[((size_t)b * Lout + lr) * Cout + col] = v;
            }
            if (lr + 8 < Lout) {
                float2 v = make_float2((float)g[mt][nt][2] + b0, (float)g[mt][nt][3] + b1);
                *(float2*)&yT[((size_t)b * Lout + lr + 8) * Cout + col] = v;
            }
        }
    }
}

// GN stats over [b][l][C]
__global__ __launch_bounds__(256)
void gn_stats_t(const float* __restrict__ x, float* __restrict__ mean,
                float* __restrict__ istd, int L, int C, int G)
{
    int blk = blockIdx.x, b = blk / G, g = blk % G;
    const float* p = x + (size_t)b * L * C + g * 16;
    float s = 0.0f, s2 = 0.0f;
    int tot = L * 16;
    for (int i = threadIdx.x; i < tot; i += 256) {
        int l = i >> 4, cc = i & 15;
        float v = p[(size_t)l * C + cc];
        s += v; s2 = fmaf(v, v, s2);
    }
    __shared__ float sa[256], sbm[256];
    int tid = threadIdx.x;
    sa[tid] = s; sbm[tid] = s2;
    __syncthreads();
    for (int o = 128; o > 0; o >>= 1) {
        if (tid < o) { sa[tid] += sa[tid + o]; sbm[tid] += sbm[tid + o]; }
        __syncthreads();
    }
    if (tid == 0) {
        float m = sa[0] / (float)tot;
        float var = sbm[0] / (float)tot - m * m;
        mean[blk] = m;
        istd[blk] = rsqrtf(var + 1e-5f);
    }
}

// GN apply + GELU + scaled fp16 2-way split -> planes
__global__ __launch_bounds__(256)
void ng_split(const float* __restrict__ x, const float* __restrict__ mean,
              const float* __restrict__ istd, const float* __restrict__ gma,
              const float* __restrict__ bta, __half* __restrict__ xs,
              size_t ps, int L, int C, int G)
{
    int b = blockIdx.y;
    size_t i4 = (size_t)blockIdx.x * 256 + threadIdx.x;
    size_t n4 = (size_t)L * C >> 2;
    if (i4 >= n4) return;
    size_t base = (size_t)b * L * C;
    float4 v = ((const float4*)(x + base))[i4];
    int cc = (int)((i4 << 2) % (size_t)C);
    int bg = b * G + (cc >> 4);
    float mu = mean[bg], is = istd[bg];
    float o[4] = {v.x, v.y, v.z, v.w};
    __half p0[4], p1[4];
    #pragma unroll
    for (int j = 0; j < 4; j++) {
        float h = gelu_f((o[j] - mu) * is * gma[cc + j] + bta[cc + j]);
        __half a = __float2half(h);
        p0[j] = a;
        p1[j] = __float2half((h - __half2float(a)) * 2048.0f);
    }
    ((uint64_t*)(xs + base))[i4]      = *(uint64_t*)p0;
    ((uint64_t*)(xs + ps + base))[i4] = *(uint64_t*)p1;
}

__global__ __launch_bounds__(256)
void ng_inplace(float* __restrict__ x, const float* __restrict__ mean,
                const float* __restrict__ istd, const float* __restrict__ gma,
                const float* __restrict__ bta, int L, int C, int G)
{
    int b = blockIdx.y;
    size_t i4 = (size_t)blockIdx.x * 256 + threadIdx.x;
    size_t n4 = (size_t)L * C >> 2;
    if (i4 >= n4) return;
    size_t base = (size_t)b * L * C;
    float4 v = ((const float4*)(x + base))[i4];
    int cc = (int)((i4 << 2) % (size_t)C);
    int bg = b * G + (cc >> 4);
    float mu = mean[bg], is = istd[bg];
    v.x = gelu_f((v.x - mu) * is * gma[cc + 0] + bta[cc + 0]);
    v.y = gelu_f((v.y - mu) * is * gma[cc + 1] + bta[cc + 1]);
    v.z = gelu_f((v.z - mu) * is * gma[cc + 2] + bta[cc + 2]);
    v.w = gelu_f((v.w - mu) * is * gma[cc + 3] + bta[cc + 3]);
    ((float4*)(x + base))[i4] = v;
}

// SIMT f32x2 GEMM tail
__global__ __launch_bounds__(128)
void gemm_nt(const float* __restrict__ A, const float* __restrict__ B,
             const float* __restrict__ bias, float* __restrict__ out, int K, int Nj)
{
    __shared__ float As[64][17], Bs[64][17];
    int tid = threadIdx.x;
    int i0 = blockIdx.y * 64, j0 = blockIdx.x * 64;
    int isub = tid >> 4, jsub = tid & 15;
    f32x2 acc[8][2];
    #pragma unroll
    for (int i = 0; i < 8; i++) { acc[i][0].u = 0ull; acc[i][1].u = 0ull; }
    for (int k0 = 0; k0 < K; k0 += 16) {
        __syncthreads();
        for (int x = tid; x < 1024; x += 128) {
            int r = x >> 4, cc = x & 15;
            As[r][cc] = A[(size_t)(i0 + r) * K + k0 + cc];
            Bs[r][cc] = B[(size_t)(j0 + r) * K + k0 + cc];
        }
        __syncthreads();
        #pragma unroll 4
        for (int k = 0; k < 16; k++) {
            f32x2 b0 = pack2(Bs[jsub * 4 + 0][k], Bs[jsub * 4 + 1][k]);
            f32x2 b1 = pack2(Bs[jsub * 4 + 2][k], Bs[jsub * 4 + 3][k]);
            #pragma unroll
            for (int ii = 0; ii < 8; ii++) {
                float a = As[isub + (ii << 3)][k];
                f32x2 a2 = pack2(a, a);
                fma2(acc[ii][0], a2, b0);
                fma2(acc[ii][1], a2, b1);
            }
        }
    }
    int j = j0 + jsub * 4;
    float bv0 = bias ? bias[j] : 0.0f, bv1 = bias ? bias[j + 1] : 0.0f;
    float bv2 = bias ? bias[j + 2] : 0.0f, bv3 = bias ? bias[j + 3] : 0.0f;
    #pragma unroll
    for (int ii = 0; ii < 8; ii++) {
        int i = i0 + isub + (ii << 3);
        float o0, o1, o2, o3;
        unpack2(acc[ii][0], o0, o1);
        unpack2(acc[ii][1], o2, o3);
        float* p = out + (size_t)i * Nj + j;
        p[0] = o0 + bv0; p[1] = o1 + bv1; p[2] = o2 + bv2; p[3] = o3 + bv3;
    }
}

__global__ __launch_bounds__(256)
void cb_norms(const float* __restrict__ cbk, float* __restrict__ cn)
{
    const float4* row = (const float4*)(cbk + (size_t)blockIdx.x * 1536);
    float s = 0.0f;
    for (int i = threadIdx.x; i < 384; i += 256) {
        float4 v = row[i];
        s += v.x * v.x + v.y * v.y + v.z * v.z + v.w * v.w;
    }
    __shared__ float sa[256];
    int tid = threadIdx.x;
    sa[tid] = s;
    __syncthreads();
    for (int o = 128; o > 0; o >>= 1) {
        if (tid < o) sa[tid] += sa[tid + o];
        __syncthreads();
    }
    if (tid == 0) cn[blockIdx.x] = sa[0];
}

__global__ __launch_bounds__(256)
void vq_argmin(const float* __restrict__ sc, const float* __restrict__ cn,
               int* __restrict__ idx, int NS)
{
    int g = blockIdx.x * 8 + (threadIdx.x >> 5);
    int lane = threadIdx.x & 31;
    if (g >= NS) return;
    const float* s = sc + (size_t)g * 1024;
    float best = 3.4e38f; int bi = 1 << 30;
    for (int j = lane; j < 1024; j += 32) {
        float d = fmaf(-2.0f, s[j], cn[j]);
        if (d < best) { best = d; bi = j; }
    }
    #pragma unroll
    for (int o = 16; o > 0; o >>= 1) {
        float ov = __shfl_xor_sync(0xffffffffu, best, o);
        int   oi = __shfl_xor_sync(0xffffffffu, bi,   o);
        if (ov < best || (ov == best && oi < bi)) { best = ov; bi = oi; }
    }
    if (lane == 0) idx[g] = bi;
}

__global__ __launch_bounds__(256)
void final_ln(const float* __restrict__ cbk, const int* __restrict__ idx,
              const float* __restrict__ pos, const float* __restrict__ mod,
              const float* __restrict__ lng, const float* __restrict__ lnb,
              float* __restrict__ out, int S, int NS)
{
    int n = blockIdx.x, s = n % S, tid = threadIdx.x;
    __shared__ float row[1536];
    __shared__ float sa[256], sbm[256];
    const float* c = cbk + (size_t)idx[n] * 1536;
    const float* p = pos + (size_t)s * 1536;
    float ls = 0.0f, ls2 = 0.0f;
    for (int e = tid; e < 1536; e += 256) {
        float v = c[e] + p[e] + mod[e];
        row[e] = v;
        ls += v; ls2 = fmaf(v, v, ls2);
    }
    sa[tid] = ls; sbm[tid] = ls2;
    __syncthreads();
    for (int o = 128; o > 0; o >>= 1) {
        if (tid < o) { sa[tid] += sa[tid + o]; sbm[tid] += sbm[tid + o]; }
        __syncthreads();
    }
    float m = sa[0] * (1.0f / 1536.0f);
    float var = sbm[0] * (1.0f / 1536.0f) - m * m;
    float r = rsqrtf(var + 1e-5f);
    for (int e = tid; e < 1536; e += 256)
        out[(size_t)n * 1536 + e] = (row[e] - m) * r * lng[e] + lnb[e];
    if (tid == 0) {
        out[(size_t)NS * 1536 + n]      = 1.0f;
        out[(size_t)NS * 1536 + NS + n] = (float)idx[n];
    }
}

extern "C" void kernel_launch(void* const* d_in, const int* in_sizes, int n_in,
                              void* d_out, int out_size)
{
    const float* wav = (const float*)d_in[0];
    const float* w0  = (const float*)d_in[1];
    const float* b0  = (const float*)d_in[2];
    const float* w1  = (const float*)d_in[3];
    const float* b1  = (const float*)d_in[4];
    const float* wr  = (const float*)d_in[5];
    const float* br  = (const float*)d_in[6];
    const float* g0  = (const float*)d_in[7];
    const float* bb0 = (const float*)d_in[8];
    const float* gr  = (const float*)d_in[9];
    const float* brr = (const float*)d_in[10];
    const float* pw  = (const float*)d_in[11];
    const float* pb  = (const float*)d_in[12];
    const float* cbk = (const float*)d_in[13];
    const float* pos = (const float*)d_in[14];
    const float* mod = (const float*)d_in[15];
    const float* lng = (const float*)d_in[16];
    const float* lnb = (const float*)d_in[17];
    float* out = (float*)d_out;

    const int B = 8;
    int Lw = in_sizes[0] / B;
    int L[7];
    L[0] = Lw / 5 + 1;
    for (int i = 1; i <= 6; i++) L[i] = L[i - 1] / 2 + 1;

    float *bufA, *bufB, *mean_, *istd_, *cn_;
    __half *xt_, *ws_;
    int *idx_;
    cudaGetSymbolAddress((void**)&bufA,  g_bufA);
    cudaGetSymbolAddress((void**)&bufB,  g_bufB);
    cudaGetSymbolAddress((void**)&xt_,   g_xt);
    cudaGetSymbolAddress((void**)&ws_,   g_ws);
    cudaGetSymbolAddress((void**)&mean_, g_mean);
    cudaGetSymbolAddress((void**)&istd_, g_istd);
    cudaGetSymbolAddress((void**)&cn_,   g_cnorm);
    cudaGetSymbolAddress((void**)&idx_,  g_idx);

    const int SMEMSZ = NSTG * BUFB;   // 208896
    cudaFuncSetAttribute(conv_mma<256>, cudaFuncAttributeMaxDynamicSharedMemorySize, SMEMSZ);
    cudaFuncSetAttribute(conv_mma<512>, cudaFuncAttributeMaxDynamicSharedMemorySize, SMEMSZ);

    cb_norms<<<1024, 256>>>(cbk, cn_);
    wprep_all<<<dim3(512, 6), 256>>>(w1, wr, ws_);

    conv0_t<<<dim3((L[0] + 15) / 16, B), 256>>>(wav, w0, b0, bufA, Lw, L[0]);
    gn_stats_t<<<B * 16, 256>>>(bufA, mean_, istd_, L[0], 256, 16);
    {
        size_t ps = (size_t)B * L[0] * 256;
        int nb = (int)(((size_t)L[0] * 256 / 4 + 255) / 256);
        ng_split<<<dim3(nb, B), 256>>>(bufA, mean_, istd_, g0, bb0, xt_, ps, L[0], 256, 16);
    }

    // layer 1 (MMA, Cin=256)
    conv_mma<256><<<dim3(8, (L[1] + 127) / 128, B), 256, SMEMSZ>>>(
        xt_, (size_t)B * L[0] * 256, ws_, 1310720, b1, bufA, 512, L[0], L[1]);
    gn_stats_t<<<B * 32, 256>>>(bufA, mean_, istd_, L[1], 512, 32);
    {
        size_t ps = (size_t)B * L[1] * 512;
        int nb = (int)(((size_t)L[1] * 512 / 4 + 255) / 256);
        ng_split<<<dim3(nb, B), 256>>>(bufA, mean_, istd_, gr, brr, xt_, ps, L[1], 512, 32);
    }

    // layers 2..6 (MMA, Cin=512)
    for (int i = 0; i < 5; i++) {
        int Lin = L[1 + i], Lo = L[2 + i];
        conv_mma<512><<<dim3(8, (Lo + 127) / 128, B), 256, SMEMSZ>>>(
            xt_, (size_t)B * Lin * 512, ws_ + 2621440 + (size_t)i * 5242880, 2621440,
            br + i * 512, bufA, 512, Lin, Lo);
        gn_stats_t<<<B * 32, 256>>>(bufA, mean_, istd_, Lo, 512, 32);
        int nb = (int)(((size_t)Lo * 512 / 4 + 255) / 256);
        if (i < 4) {
            size_t ps = (size_t)B * Lo * 512;
            ng_split<<<dim3(nb, B), 256>>>(bufA, mean_, istd_, gr + (i + 1) * 512,
                                           brr + (i + 1) * 512, xt_, ps, Lo, 512, 32);
        } else {
            ng_inplace<<<dim3(nb, B), 256>>>(bufA, mean_, istd_, gr + 5 * 512,
                                             brr + 5 * 512, Lo, 512, 32);
        }
    }

    int S = L[6];           // 976
    int NS = B * S;         // 7808

    // projection: feats[NS][1536]
    gemm_nt<<<dim3(1536 / 64, NS / 64), 128>>>(bufA, pw, pb, bufB, 512, 1536);

    // VQ
    float* sc = (float*)xt_;
    gemm_nt<<<dim3(1024 / 64, NS / 64), 128>>>(bufB, cbk, nullptr, sc, 1536, 1024);
    vq_argmin<<<(NS + 7) / 8, 256>>>(sc, cn_, idx_, NS);

    final_ln<<<NS, 256>>>(cbk, idx_, pos, mod, lng, lnb, out, S, NS);
}